// round 10
// baseline (speedup 1.0000x reference)
#include <cuda_runtime.h>
#include <cuda_fp16.h>
#include <math.h>
#include <stdint.h>

// ---------------------------------------------------------------------------
// Problem dims
// ---------------------------------------------------------------------------
#define T_STEPS 16
#define B_SZ    32
#define C_IN    2048
#define MEM_SZ  512
#define N_CLS   8
#define C_CAM   1000
#define HW      49
#define PADHW   81
#define KX      (C_IN*9)          // 18432
#define KH      (MEM_SZ*9)        // 4608
#define WROW    ((C_IN+MEM_SZ)*9) // 23040 original main-weight row stride
#define MBIG    (T_STEPS*B_SZ*HW) // 25088
#define MSTEP   (B_SZ*HW)         // 1568
#define TB      (T_STEPS*B_SZ)    // 512
#define NFUSED  (3*MEM_SZ)        // 1536
#define XROW    (PADHW*C_IN)      // halves per tb in xT
#define HROW    (PADHW*MEM_SZ)    // halves per b in hT

// ---------------------------------------------------------------------------
// Static device scratch
// ---------------------------------------------------------------------------
__device__ __half g_xT[(size_t)TB * XROW];
__device__ __half g_hT[B_SZ * HROW];
__device__ __half g_wx[(size_t)3 * MEM_SZ * KX];
__device__ __half g_wh[(size_t)3 * MEM_SZ * KH];
__device__ float  g_wsx[3 * KX];
__device__ float  g_preS0[MBIG];
__device__ float  g_preS1[MBIG];
__device__ float  g_preS2[MBIG];
__device__ float  g_attmap[MBIG];
__device__ float  g_s[MBIG];
__device__ float  g_pooled[TB * C_IN];
__device__ float  g_logits[TB * C_CAM];
__device__ float  g_preM[(size_t)MBIG * NFUSED];
__device__ float  g_cstate[MSTEP * MEM_SZ];

__constant__ int c_border[32] = {
    0,1,2,3,4,5,6,7,8,
    72,73,74,75,76,77,78,79,80,
    9,17, 18,26, 27,35, 36,44, 45,53, 54,62, 63,71
};

__device__ __forceinline__ float sigmoidf_(float x) { return 1.0f / (1.0f + expf(-x)); }

// ---------------------------------------------------------------------------
// Pad + transpose x -> channels-last fp16 xT, zero borders, compute pooled
// grid (TB, C_IN/32), 256 thr
// ---------------------------------------------------------------------------
__global__ void pad_xT_pool(const float* __restrict__ x) {
    __shared__ float tile[32][50];
    int tb = blockIdx.x, c0 = blockIdx.y * 32;
    int tid = threadIdx.x;
    for (int idx = tid; idx < 32 * HW; idx += 256) {
        int r = idx / HW, q = idx - HW * r;
        tile[r][q] = x[((size_t)tb * C_IN + c0 + r) * HW + q];
    }
    __syncthreads();
    for (int idx = tid; idx < HW * 32; idx += 256) {
        int q = idx >> 5, cl = idx & 31;
        int p = (q / 7 + 1) * 9 + (q % 7) + 1;
        g_xT[(size_t)tb * XROW + (size_t)p * C_IN + c0 + cl] = __float2half_rn(tile[cl][q]);
    }
    for (int idx = tid; idx < 1024; idx += 256) {
        int bp = idx >> 5, cl = idx & 31;
        g_xT[(size_t)tb * XROW + (size_t)c_border[bp] * C_IN + c0 + cl] = __float2half_rn(0.f);
    }
    if (tid < 32) {
        float s = 0.f;
        #pragma unroll
        for (int q = 0; q < HW; q++) s += tile[tid][q];
        g_pooled[tb * C_IN + c0 + tid] = s * (1.0f / 49.0f);
    }
}

// ---------------------------------------------------------------------------
// One kernel: reorder wx/wh/ws to (tap, c) fp16/fp32 + zero hT/cstate
// ---------------------------------------------------------------------------
__global__ void reorder_all(const float* __restrict__ W0, const float* __restrict__ W1,
                            const float* __restrict__ W2,
                            const float* __restrict__ Wsfi, const float* __restrict__ Wsc,
                            const float* __restrict__ Wso) {
    size_t i = (size_t)blockIdx.x * 256 + threadIdx.x;
    const size_t S1 = (size_t)3 * MEM_SZ * C_IN;
    const size_t S2 = S1 + (size_t)3 * MEM_SZ * MEM_SZ;
    const size_t S3 = S2 + (size_t)3 * C_IN;
    const size_t S4 = S3 + (size_t)B_SZ * HROW;
    const size_t S5 = S4 + (size_t)MSTEP * MEM_SZ;
    if (i < S1) {
        int c = (int)(i & (C_IN - 1));
        int r = (int)(i >> 11);
        int n = r & (MEM_SZ - 1);
        int gate = r >> 9;
        const float* W = (gate == 0) ? W0 : (gate == 1 ? W1 : W2);
        const float* src = W + (size_t)n * WROW + (size_t)c * 9;
        __half* dst = g_wx + ((size_t)gate * MEM_SZ + n) * KX + c;
        #pragma unroll
        for (int tap = 0; tap < 9; tap++) dst[(size_t)tap * C_IN] = __float2half_rn(src[tap]);
    } else if (i < S2) {
        size_t lin = i - S1;
        int c = (int)(lin & (MEM_SZ - 1));
        int r = (int)(lin >> 9);
        int n = r & (MEM_SZ - 1);
        int gate = r >> 9;
        const float* W = (gate == 0) ? W0 : (gate == 1 ? W1 : W2);
        const float* src = W + (size_t)n * WROW + (size_t)(C_IN + c) * 9;
        __half* dst = g_wh + ((size_t)gate * MEM_SZ + n) * KH + c;
        #pragma unroll
        for (int tap = 0; tap < 9; tap++) dst[(size_t)tap * MEM_SZ] = __float2half_rn(src[tap]);
    } else if (i < S3) {
        int lin = (int)(i - S2);
        int gate = lin >> 11, c = lin & (C_IN - 1);
        const float* W = (gate == 0) ? Wsfi : (gate == 1 ? Wsc : Wso);
        #pragma unroll
        for (int tap = 0; tap < 9; tap++)
            g_wsx[gate * KX + tap * C_IN + c] = W[c * 9 + tap];
    } else if (i < S4) {
        g_hT[i - S3] = __float2half_rn(0.f);
    } else if (i < S5) {
        g_cstate[i - S4] = 0.f;
    }
}

// ---------------------------------------------------------------------------
// CAM logits as a tiled fp32 GEMM: logits[512,1000] = pooled[512,2048] @ W_cam^T
// block 64tb x 64j, 256 thr, K-chunks of 16
// ---------------------------------------------------------------------------
__global__ __launch_bounds__(256) void logits_gemm(const float* __restrict__ W_cam) {
    __shared__ float As[16][65];
    __shared__ float Bs[16][65];
    int j0 = blockIdx.x * 64, t0 = blockIdx.y * 64;
    int tid = threadIdx.x;
    int tx = tid & 15, ty = tid >> 4;
    float acc[4][4] = {};
    for (int k0 = 0; k0 < C_IN; k0 += 16) {
        #pragma unroll
        for (int r = 0; r < 4; r++) {
            int lin = tid + 256 * r;
            int m = lin >> 4, kk = lin & 15;
            As[kk][m] = g_pooled[(t0 + m) * C_IN + k0 + kk];
            int j = j0 + m;
            Bs[kk][m] = (j < C_CAM) ? W_cam[(size_t)j * C_IN + k0 + kk] : 0.f;
        }
        __syncthreads();
        #pragma unroll
        for (int kk = 0; kk < 16; kk++) {
            float a[4], b[4];
            #pragma unroll
            for (int u = 0; u < 4; u++) a[u] = As[kk][ty * 4 + u];
            #pragma unroll
            for (int u = 0; u < 4; u++) b[u] = Bs[kk][tx * 4 + u];
            #pragma unroll
            for (int u = 0; u < 4; u++)
                #pragma unroll
                for (int v = 0; v < 4; v++) acc[u][v] += a[u] * b[v];
        }
        __syncthreads();
    }
    #pragma unroll
    for (int u = 0; u < 4; u++)
        #pragma unroll
        for (int v = 0; v < 4; v++) {
            int j = j0 + tx * 4 + v;
            if (j < C_CAM)
                g_logits[(t0 + ty * 4 + u) * C_CAM + j] = acc[u][v];
        }
}

// ---------------------------------------------------------------------------
// Per-tb fused: argmax(logits) + CAM + softmax(attmap) + preS gate pre-acts
// grid TB, 256 thr
// ---------------------------------------------------------------------------
__global__ __launch_bounds__(256) void fused_tb(const float* __restrict__ x,
                                                const float* __restrict__ W_cam) {
    int tb = blockIdx.x, tid = threadIdx.x;
    int wid = tid >> 5, lane = tid & 31;
    __shared__ float ws[3 * C_IN];
    __shared__ float camv[HW];
    __shared__ float red[256];
    __shared__ int   redi[256];

    // ---- argmax over logits ----
    float best = -INFINITY; int bi = 0;
    for (int j = tid; j < C_CAM; j += 256) {
        float v = g_logits[tb * C_CAM + j];
        if (v > best) { best = v; bi = j; }
    }
    red[tid] = best; redi[tid] = bi; __syncthreads();
    for (int s = 128; s > 0; s >>= 1) {
        if (tid < s) {
            float v2 = red[tid + s]; int i2 = redi[tid + s];
            if (v2 > red[tid] || (v2 == red[tid] && i2 < redi[tid])) { red[tid] = v2; redi[tid] = i2; }
        }
        __syncthreads();
    }
    int cls = redi[0];
    __syncthreads();

    // ---- CAM map ----
    const float* wsel = W_cam + (size_t)cls * C_IN;
    for (int it = 0; it < 7; it++) {
        int hw = wid + 8 * it;
        if (hw < HW) {
            const float* xp = x + (size_t)tb * C_IN * HW + hw;
            float acc = 0.f;
            for (int c = lane; c < C_IN; c += 32) acc += wsel[c] * xp[(size_t)c * HW];
            #pragma unroll
            for (int o = 16; o > 0; o >>= 1) acc += __shfl_down_sync(0xffffffffu, acc, o);
            if (lane == 0) camv[hw] = acc;
        }
    }
    __syncthreads();

    // ---- softmax -> attmap ----
    red[tid] = (tid < HW) ? camv[tid] : -INFINITY; __syncthreads();
    for (int s = 128; s > 0; s >>= 1) { if (tid < s) red[tid] = fmaxf(red[tid], red[tid + s]); __syncthreads(); }
    float mx = red[0]; __syncthreads();
    float e = (tid < HW) ? expf(camv[tid] - mx) : 0.f;
    red[tid] = e; __syncthreads();
    for (int s = 128; s > 0; s >>= 1) { if (tid < s) red[tid] += red[tid + s]; __syncthreads(); }
    if (tid < HW) g_attmap[tb * HW + tid] = e / red[0];

    // ---- preS: attention-gate x contributions ----
    float acc[7][3];
    #pragma unroll
    for (int j = 0; j < 7; j++) { acc[j][0] = 0.f; acc[j][1] = 0.f; acc[j][2] = 0.f; }
    const __half* xb = g_xT + (size_t)tb * XROW;
    for (int tap = 0; tap < 9; tap++) {
        __syncthreads();
        for (int idx = tid; idx < 3 * C_IN; idx += 256) {
            int g = idx >> 11, c = idx & (C_IN - 1);
            ws[idx] = g_wsx[g * KX + tap * C_IN + c];
        }
        __syncthreads();
        int dr = tap / 3, dc = tap - 3 * dr;
        #pragma unroll
        for (int j = 0; j < 7; j++) {
            int hw = wid + 8 * j;
            if (hw >= HW) break;
            int hh = hw / 7, wwp = hw - 7 * hh;
            const __half* xr = xb + (size_t)((hh + dr) * 9 + wwp + dc) * C_IN;
            float a0 = 0.f, a1 = 0.f, a2 = 0.f;
            for (int c = lane; c < C_IN; c += 32) {
                float v = __half2float(xr[c]);
                a0 += v * ws[c];
                a1 += v * ws[C_IN + c];
                a2 += v * ws[2 * C_IN + c];
            }
            acc[j][0] += a0; acc[j][1] += a1; acc[j][2] += a2;
        }
    }
    #pragma unroll
    for (int j = 0; j < 7; j++) {
        int hw = wid + 8 * j;
        if (hw >= HW) break;
        float a0 = acc[j][0], a1 = acc[j][1], a2 = acc[j][2];
        #pragma unroll
        for (int o = 16; o > 0; o >>= 1) {
            a0 += __shfl_down_sync(0xffffffffu, a0, o);
            a1 += __shfl_down_sync(0xffffffffu, a1, o);
            a2 += __shfl_down_sync(0xffffffffu, a2, o);
        }
        if (lane == 0) {
            int m = tb * HW + hw;
            g_preS0[m] = a0; g_preS1[m] = a1; g_preS2[m] = a2;
        }
    }
}

// ---------------------------------------------------------------------------
// Fused attention recurrence (16 steps, state in smem)
// ---------------------------------------------------------------------------
__global__ void att_fused(const float* __restrict__ Wfi, const float* __restrict__ Wc,
                          const float* __restrict__ Wo,
                          const float* __restrict__ bfi, const float* __restrict__ bc,
                          const float* __restrict__ bo) {
    int b = blockIdx.x, tid = threadIdx.x;
    __shared__ float ap[HW], av[HW], csh[HW], red[64];
    if (tid < HW) { ap[tid] = 0.f; csh[tid] = 0.f; }
    __syncthreads();
    for (int t = 0; t < T_STEPS; t++) {
        if (tid < HW) {
            int h = tid / 7, w = tid % 7;
            float efi = 0.f, ec = 0.f, eo = 0.f;
            #pragma unroll
            for (int kh = 0; kh < 3; kh++)
                #pragma unroll
                for (int kw = 0; kw < 3; kw++) {
                    int hh = h + kh - 1, ww = w + kw - 1;
                    if (hh >= 0 && hh < 7 && ww >= 0 && ww < 7) {
                        float aval = ap[hh * 7 + ww];
                        int off = KX + kh * 3 + kw;
                        efi += aval * Wfi[off];
                        ec  += aval * Wc[off];
                        eo  += aval * Wo[off];
                    }
                }
            int base = (t * B_SZ + b) * HW + tid;
            float fi = sigmoidf_(g_preS0[base] + efi + bfi[0]);
            float o  = sigmoidf_(g_preS2[base] + eo + bo[0]);
            float cc = tanhf(g_preS1[base] + ec + bc[0]);
            float cs = fi * csh[tid] + (1.0f - fi) * cc;
            csh[tid] = cs;
            av[tid] = o * tanhf(cs) * g_attmap[base];
        }
        __syncthreads();
        float m = (tid < HW) ? av[tid] : -INFINITY;
        red[tid] = m; __syncthreads();
        for (int s = 32; s > 0; s >>= 1) { if (tid < s) red[tid] = fmaxf(red[tid], red[tid + s]); __syncthreads(); }
        float mx = red[0]; __syncthreads();
        float e = (tid < HW) ? expf(av[tid] - mx) : 0.f;
        red[tid] = e; __syncthreads();
        for (int s = 32; s > 0; s >>= 1) { if (tid < s) red[tid] += red[tid + s]; __syncthreads(); }
        if (tid < HW) {
            g_s[(t * B_SZ + b) * HW + tid] = e / red[0];
            ap[tid] = av[tid];
        }
        __syncthreads();
    }
}

// ---------------------------------------------------------------------------
// x_att scaling (coalesced over c), fp16 in/out
// ---------------------------------------------------------------------------
__global__ void scale_x() {
    size_t lin = (size_t)blockIdx.x * 256 + threadIdx.x;
    if (lin >= (size_t)TB * HW * C_IN) return;
    int c  = lin & (C_IN - 1);
    int rc = (int)(lin >> 11);
    int tb = rc / HW, hw = rc - HW * tb;
    float sc = g_s[rc];
    int p = (hw / 7 + 1) * 9 + (hw % 7) + 1;
    size_t a = (size_t)tb * XROW + (size_t)p * C_IN + c;
    g_xT[a] = __float2half_rn(__half2float(g_xT[a]) * sc);
}

// ---------------------------------------------------------------------------
// FP16 implicit GEMM, 256(M)x128(N)x64(K), 8 warps (4m x 2n), warp 64x64.
// Big-M kernel for the x-part conv of all timesteps.
// ---------------------------------------------------------------------------
#define STGB2 49152
#define PIPE 3

__global__ __launch_bounds__(256, 1) void conv_gemm_fp16_m256(
    const __half* __restrict__ Apad, int Crow, int cshift, int M, int KT, int Kfull,
    const __half* __restrict__ Wbase, float* __restrict__ Out)
{
    extern __shared__ char smc[];
    const int tid  = threadIdx.x;
    const int m0   = blockIdx.y * 256;
    const int gate = blockIdx.x >> 2;
    const int n0in = (blockIdx.x & 3) * 128;
    const __half* Wg = Wbase + ((size_t)gate * MEM_SZ + n0in) * Kfull;

    const int rlo = tid >> 3;
    const int kq  = (tid & 7) * 8;
    const int stChunk = ((tid & 7) ^ (rlo & 7)) << 4;

    size_t rowoff[8]; int asz[8];
    #pragma unroll
    for (int i = 0; i < 8; i++) {
        int m = m0 + rlo + 32 * i;
        if (m < M) {
            int tb = m / HW, hw = m - HW * tb;
            rowoff[i] = ((size_t)tb * PADHW + (size_t)((hw / 7) * 9 + hw % 7)) * Crow;
            asz[i] = 16;
        } else { rowoff[i] = 0; asz[i] = 0; }
    }

    const int lane = tid & 31;
    const int wid  = tid >> 5;
    const int g    = lane >> 2;
    const int cq   = lane & 3;
    const int wmB  = (wid & 3) * 64;
    const int wnB  = (wid >> 2) * 64;

    float acc[4][8][4];
    #pragma unroll
    for (int a = 0; a < 4; a++)
        #pragma unroll
        for (int b = 0; b < 8; b++)
            #pragma unroll
            for (int c = 0; c < 4; c++) acc[a][b][c] = 0.f;

    auto issue = [&](int s, int kt) {
        char* As_ = smc + s * STGB2;
        char* Bs_ = As_ + 32768;
        uint32_t aB = (uint32_t)__cvta_generic_to_shared(As_);
        uint32_t bB = (uint32_t)__cvta_generic_to_shared(Bs_);
        int k0  = kt * 64;
        int tap = k0 >> cshift;
        int c0  = k0 & (Crow - 1);
        int dr  = tap / 3, dc = tap - 3 * dr;
        size_t poff = (size_t)(dr * 9 + dc) * Crow + c0 + kq;
        #pragma unroll
        for (int i = 0; i < 8; i++) {
            const __half* src = Apad + rowoff[i] + poff;
            uint32_t dst = aB + (uint32_t)((rlo + 32 * i) * 128 + stChunk);
            asm volatile("cp.async.cg.shared.global [%0], [%1], 16, %2;\n"
                         :: "r"(dst), "l"(src), "r"(asz[i]));
        }
        #pragma unroll
        for (int i = 0; i < 4; i++) {
            int nl = rlo + 32 * i;
            const __half* src = Wg + (size_t)nl * Kfull + k0 + kq;
            uint32_t dst = bB + (uint32_t)(nl * 128 + stChunk);
            asm volatile("cp.async.cg.shared.global [%0], [%1], 16;\n"
                         :: "r"(dst), "l"(src));
        }
        asm volatile("cp.async.commit_group;\n");
    };

    #pragma unroll
    for (int s = 0; s < PIPE - 1; s++)
        if (s < KT) issue(s, s);

    for (int kt = 0; kt < KT; kt++) {
        if (kt + 1 < KT) asm volatile("cp.async.wait_group 1;\n" ::: "memory");
        else             asm volatile("cp.async.wait_group 0;\n" ::: "memory");
        __syncthreads();
        if (kt + PIPE - 1 < KT) issue((kt + PIPE - 1) % PIPE, kt + PIPE - 1);

        const char* As_ = smc + (kt % PIPE) * STGB2;
        const char* Bs_ = As_ + 32768;

        #pragma unroll
        for (int ks = 0; ks < 4; ks++) {
            const int ch0 = (((2 * ks)     ^ g) << 4) + 4 * cq;
            const int ch1 = (((2 * ks + 1) ^ g) << 4) + 4 * cq;
            unsigned af[4][4], bf[8][2];
            #pragma unroll
            for (int mt = 0; mt < 4; mt++) {
                const char* r0p = As_ + (wmB + mt * 16 + g) * 128;
                const char* r1p = r0p + 8 * 128;
                af[mt][0] = *(const uint32_t*)(r0p + ch0);
                af[mt][1] = *(const uint32_t*)(r1p + ch0);
                af[mt][2] = *(const uint32_t*)(r0p + ch1);
                af[mt][3] = *(const uint32_t*)(r1p + ch1);
            }
            #pragma unroll
            for (int nt = 0; nt < 8; nt++) {
                const char* np = Bs_ + (wnB + nt * 8 + g) * 128;
                bf[nt][0] = *(const uint32_t*)(np + ch0);
                bf[nt][1] = *(const uint32_t*)(np + ch1);
            }
            #pragma unroll
            for (int mt = 0; mt < 4; mt++)
                #pragma unroll
                for (int nt = 0; nt < 8; nt++) {
                    asm volatile(
                        "mma.sync.aligned.m16n8k16.row.col.f32.f16.f16.f32 "
                        "{%0,%1,%2,%3}, {%4,%5,%6,%7}, {%8,%9}, {%0,%1,%2,%3};\n"
                        : "+f"(acc[mt][nt][0]), "+f"(acc[mt][nt][1]),
                          "+f"(acc[mt][nt][2]), "+f"(acc[mt][nt][3])
                        : "r"(af[mt][0]), "r"(af[mt][1]), "r"(af[mt][2]), "r"(af[mt][3]),
                          "r"(bf[nt][0]), "r"(bf[nt][1]));
                }
        }
        __syncthreads();
    }

    const size_t colBase = (size_t)(gate * MEM_SZ + n0in);
    #pragma unroll
    for (int mt = 0; mt < 4; mt++) {
        int r0 = m0 + wmB + mt * 16 + g;
        #pragma unroll
        for (int nt = 0; nt < 8; nt++) {
            size_t co = colBase + wnB + nt * 8 + cq * 2;
            if (r0 < M) {
                float2 v = make_float2(acc[mt][nt][0], acc[mt][nt][1]);
                *(float2*)&Out[(size_t)r0 * NFUSED + co] = v;
            }
            if (r0 + 8 < M) {
                float2 v = make_float2(acc[mt][nt][2], acc[mt][nt][3]);
                *(float2*)&Out[(size_t)(r0 + 8) * NFUSED + co] = v;
            }
        }
    }
}

// ---------------------------------------------------------------------------
// h-chain: fused h-GEMM (128m x 192n-eff [64n x 3 gates] x 64k) + gate epilogue
// grid (8 nb, 13 mb), 256 thr, 1 CTA/SM, PIPE=3
// ---------------------------------------------------------------------------
#define HST   40960   // A 128x64x2 = 16KB + B 192x64x2 = 24KB
#define HSMEM (PIPE * HST)
#define OST   196     // epilogue smem row stride (floats)

__global__ __launch_bounds__(256, 1) void h_gemm_gates(
    int t, const float* __restrict__ bfi, const float* __restrict__ bc,
    const float* __restrict__ bo)
{
    extern __shared__ char smc[];
    const int tid = threadIdx.x;
    const int nb  = blockIdx.x;          // 0..7 (64 n-values per block)
    const int m0  = blockIdx.y * 128;

    const int rlo = tid >> 3;
    const int kq  = (tid & 7) * 8;
    const int stChunk = ((tid & 7) ^ (rlo & 7)) << 4;

    size_t rowoff[4]; int asz[4];
    #pragma unroll
    for (int i = 0; i < 4; i++) {
        int m = m0 + rlo + 32 * i;
        if (m < MSTEP) {
            int b = m / HW, hw = m - HW * b;
            rowoff[i] = ((size_t)b * PADHW + (size_t)((hw / 7) * 9 + hw % 7)) * MEM_SZ;
            asz[i] = 16;
        } else { rowoff[i] = 0; asz[i] = 0; }
    }
    const __half* bsrc[6];
    #pragma unroll
    for (int i = 0; i < 6; i++) {
        int j = rlo + 32 * i;             // B smem row 0..191
        int gate = j >> 6, jj = j & 63;
        bsrc[i] = g_wh + ((size_t)(gate * MEM_SZ + nb * 64 + jj)) * KH;
    }

    const int lane = tid & 31;
    const int wid  = tid >> 5;
    const int g    = lane >> 2;
    const int cq   = lane & 3;
    const int wmB  = (wid & 1) * 64;
    const int wnB  = (wid >> 1) * 48;

    float acc[4][6][4];
    #pragma unroll
    for (int a = 0; a < 4; a++)
        #pragma unroll
        for (int b = 0; b < 6; b++)
            #pragma unroll
            for (int c = 0; c < 4; c++) acc[a][b][c] = 0.f;

    auto issue = [&](int s, int kt) {
        char* As_ = smc + s * HST;
        char* Bs_ = As_ + 16384;
        uint32_t aB = (uint32_t)__cvta_generic_to_shared(As_);
        uint32_t bB = (uint32_t)__cvta_generic_to_shared(Bs_);
        int k0  = kt * 64;
        int tap = k0 >> 9;
        int c0  = k0 & (MEM_SZ - 1);
        int dr  = tap / 3, dc = tap - 3 * dr;
        size_t poff = (size_t)(dr * 9 + dc) * MEM_SZ + c0 + kq;
        #pragma unroll
        for (int i = 0; i < 4; i++) {
            const __half* src = g_hT + rowoff[i] + poff;
            uint32_t dst = aB + (uint32_t)((rlo + 32 * i) * 128 + stChunk);
            asm volatile("cp.async.cg.shared.global [%0], [%1], 16, %2;\n"
                         :: "r"(dst), "l"(src), "r"(asz[i]));
        }
        #pragma unroll
        for (int i = 0; i < 6; i++) {
            const __half* src = bsrc[i] + k0 + kq;
            uint32_t dst = bB + (uint32_t)((rlo + 32 * i) * 128 + stChunk);
            asm volatile("cp.async.cg.shared.global [%0], [%1], 16;\n"
                         :: "r"(dst), "l"(src));
        }
        asm volatile("cp.async.commit_group;\n");
    };

    const int KT = KH / 64;   // 72
    #pragma unroll
    for (int s = 0; s < PIPE - 1; s++) issue(s, s);

    for (int kt = 0; kt < KT; kt++) {
        if (kt + 1 < KT) asm volatile("cp.async.wait_group 1;\n" ::: "memory");
        else             asm volatile("cp.async.wait_group 0;\n" ::: "memory");
        __syncthreads();
        if (kt + PIPE - 1 < KT) issue((kt + PIPE - 1) % PIPE, kt + PIPE - 1);

        const char* As_ = smc + (kt % PIPE) * HST;
        const char* Bs_ = As_ + 16384;

        #pragma unroll
        for (int ks = 0; ks < 4; ks++) {
            const int ch0 = (((2 * ks)     ^ g) << 4) + 4 * cq;
            const int ch1 = (((2 * ks + 1) ^ g) << 4) + 4 * cq;
            unsigned af[4][4], bf[6][2];
            #pragma unroll
            for (int mt = 0; mt < 4; mt++) {
                const char* r0p = As_ + (wmB + mt * 16 + g) * 128;
                const char* r1p = r0p + 8 * 128;
                af[mt][0] = *(const uint32_t*)(r0p + ch0);
                af[mt][1] = *(const uint32_t*)(r1p + ch0);
                af[mt][2] = *(const uint32_t*)(r0p + ch1);
                af[mt][3] = *(const uint32_t*)(r1p + ch1);
            }
            #pragma unroll
            for (int nt = 0; nt < 6; nt++) {
                const char* np = Bs_ + (wnB + nt * 8 + g) * 128;
                bf[nt][0] = *(const uint32_t*)(np + ch0);
                bf[nt][1] = *(const uint32_t*)(np + ch1);
            }
            #pragma unroll
            for (int mt = 0; mt < 4; mt++)
                #pragma unroll
                for (int nt = 0; nt < 6; nt++) {
                    asm volatile(
                        "mma.sync.aligned.m16n8k16.row.col.f32.f16.f16.f32 "
                        "{%0,%1,%2,%3}, {%4,%5,%6,%7}, {%8,%9}, {%0,%1,%2,%3};\n"
                        : "+f"(acc[mt][nt][0]), "+f"(acc[mt][nt][1]),
                          "+f"(acc[mt][nt][2]), "+f"(acc[mt][nt][3])
                        : "r"(af[mt][0]), "r"(af[mt][1]), "r"(af[mt][2]), "r"(af[mt][3]),
                          "r"(bf[nt][0]), "r"(bf[nt][1]));
                }
        }
        __syncthreads();
    }

    // ---- epilogue: stash GEMM tile in smem, then fused gate update ----
    float* Osm = (float*)smc;            // reuse pipeline smem (128 x 196 floats)
    #pragma unroll
    for (int mt = 0; mt < 4; mt++) {
        int r = wmB + mt * 16 + g;
        #pragma unroll
        for (int nt = 0; nt < 6; nt++) {
            int co = wnB + nt * 8 + cq * 2;
            *(float2*)&Osm[r * OST + co]       = make_float2(acc[mt][nt][0], acc[mt][nt][1]);
            *(float2*)&Osm[(r + 8) * OST + co] = make_float2(acc[mt][nt][2], acc[mt][nt][3]);
        }
    }
    __syncthreads();

    #pragma unroll
    for (int it = 0; it < 32; it++) {
        int idx = tid + 256 * it;
        int ml = idx >> 6, nl = idx & 63;
        int m = m0 + ml;
        if (m >= MSTEP) continue;
        float g0 = Osm[ml * OST + nl];
        float g1 = Osm[ml * OST + 64 + nl];
        float g2 = Osm[ml * OST + 128 + nl];
        int n = nb * 64 + nl;
        size_t pOff = ((size_t)(t * MSTEP + m)) * NFUSED;
        float pfi = g_preM[pOff + n]        + g0 + bfi[n];
        float pc  = g_preM[pOff + 512 + n]  + g1 + bc[n];
        float po  = g_preM[pOff + 1024 + n] + g2 + bo[n];
        float fi = sigmoidf_(pfi);
        float o  = sigmoidf_(po);
        int lin = m * MEM_SZ + n;
        float cn = fi * g_cstate[lin] + (1.0f - fi) * tanhf(pc);
        g_cstate[lin] = cn;
        float h = o * tanhf(cn);
        int b = m / HW, hw = m - HW * b;
        int p = (hw / 7 + 1) * 9 + (hw % 7) + 1;
        g_hT[(size_t)b * HROW + (size_t)p * MEM_SZ + n] = __float2half_rn(h);
    }
}

// ---------------------------------------------------------------------------
// Step 0 gate update (h = 0, cstate = 0 -> no h-GEMM needed)
// ---------------------------------------------------------------------------
__global__ void gate0_kernel(const float* __restrict__ bfi,
                             const float* __restrict__ bc, const float* __restrict__ bo) {
    int lin = blockIdx.x * 256 + threadIdx.x;
    if (lin >= MSTEP * MEM_SZ) return;
    int n = lin & (MEM_SZ - 1);
    int m = lin >> 9;
    int b = m / HW, hw = m - HW * b;
    size_t pOff = (size_t)m * NFUSED;
    float pfi = g_preM[pOff + n]        + bfi[n];
    float pc  = g_preM[pOff + 512 + n]  + bc[n];
    float po  = g_preM[pOff + 1024 + n] + bo[n];
    float fi = sigmoidf_(pfi);
    float o  = sigmoidf_(po);
    float cn = (1.0f - fi) * tanhf(pc);
    g_cstate[lin] = cn;
    float h = o * tanhf(cn);
    int p = (hw / 7 + 1) * 9 + (hw % 7) + 1;
    g_hT[(size_t)b * HROW + (size_t)p * MEM_SZ + n] = __float2half_rn(h);
}

// ---------------------------------------------------------------------------
// Final: feats = mean_hw(h); logits = feats @ W_fc^T + b_fc
// ---------------------------------------------------------------------------
__global__ void final_kernel(const float* __restrict__ W_fc, const float* __restrict__ b_fc,
                             float* __restrict__ logitsOut, float* __restrict__ featsOut) {
    int b = blockIdx.x, n = threadIdx.x;
    const __half* hb = &g_hT[(size_t)b * HROW];
    float s = 0.f;
    #pragma unroll
    for (int hh = 1; hh <= 7; hh++)
        #pragma unroll
        for (int ww = 1; ww <= 7; ww++) s += __half2float(hb[(size_t)(hh * 9 + ww) * MEM_SZ + n]);
    float f = s * (1.0f / 49.0f);
    __shared__ float fs[MEM_SZ];
    fs[n] = f;
    if (featsOut) featsOut[b * MEM_SZ + n] = f;
    __syncthreads();
    if (n < N_CLS && logitsOut) {
        float acc = b_fc[n];
        for (int k = 0; k < MEM_SZ; k++) acc += fs[k] * W_fc[n * MEM_SZ + k];
        logitsOut[b * N_CLS + n] = acc;
    }
}

// ---------------------------------------------------------------------------
// Host launcher
// ---------------------------------------------------------------------------
extern "C" void kernel_launch(void* const* d_in, const int* in_sizes, int n_in,
                              void* d_out, int out_size) {
    const float* x     = (const float*)d_in[0];
    const float* W_fi  = (const float*)d_in[1];
    const float* b_fi  = (const float*)d_in[2];
    const float* W_c   = (const float*)d_in[3];
    const float* b_c   = (const float*)d_in[4];
    const float* W_o   = (const float*)d_in[5];
    const float* b_o   = (const float*)d_in[6];
    const float* Ws_fi = (const float*)d_in[7];
    const float* bs_fi = (const float*)d_in[8];
    const float* Ws_c  = (const float*)d_in[9];
    const float* bs_c  = (const float*)d_in[10];
    const float* Ws_o  = (const float*)d_in[11];
    const float* bs_o  = (const float*)d_in[12];
    const float* W_cam = (const float*)d_in[13];
    const float* W_fc  = (const float*)d_in[14];
    const float* b_fc  = (const float*)d_in[15];

    __half* xT; cudaGetSymbolAddress((void**)&xT, g_xT);
    __half* wx; cudaGetSymbolAddress((void**)&wx, g_wx);
    float*  pm; cudaGetSymbolAddress((void**)&pm, g_preM);

    const int SMEM_BYTES2 = PIPE * STGB2;   // 147456 (big-M kernel)
    cudaFuncSetAttribute(conv_gemm_fp16_m256, cudaFuncAttributeMaxDynamicSharedMemorySize, SMEM_BYTES2);
    cudaFuncSetAttribute(h_gemm_gates, cudaFuncAttributeMaxDynamicSharedMemorySize, HSMEM);

    float* outF = (float*)d_out;
    float* lp = nullptr; float* fp = nullptr;
    if (out_size >= B_SZ * N_CLS + B_SZ * MEM_SZ) { lp = outF; fp = outF + B_SZ * N_CLS; }
    else if (out_size == B_SZ * MEM_SZ)           { fp = outF; }
    else                                          { lp = outF; }

    // 1. pad + transpose x (fp16, borders, pooled)
    {
        dim3 grid(TB, C_IN / 32);
        pad_xT_pool<<<grid, 256>>>(x);
    }
    // 2. reorder all weights + zero recurrent state
    {
        const size_t TOT = (size_t)3 * MEM_SZ * C_IN + (size_t)3 * MEM_SZ * MEM_SZ
                         + (size_t)3 * C_IN + (size_t)B_SZ * HROW + (size_t)MSTEP * MEM_SZ;
        reorder_all<<<(int)((TOT + 255) / 256), 256>>>(W_fi, W_c, W_o, Ws_fi, Ws_c, Ws_o);
    }
    // 3. CAM logits (tiled GEMM)
    {
        dim3 grid((C_CAM + 63) / 64, TB / 64);
        logits_gemm<<<grid, 256>>>(W_cam);
    }
    // 4. argmax + CAM map + softmax + preS (per tb)
    fused_tb<<<TB, 256>>>(x, W_cam);
    // 5. fused attention recurrence
    att_fused<<<B_SZ, 64>>>(Ws_fi, Ws_c, Ws_o, bs_fi, bs_c, bs_o);
    // 6. attention scaling
    scale_x<<<(int)(((size_t)TB * HW * C_IN + 255) / 256), 256>>>();
    // 7. giant parallel GEMM (x part, all t, 3 gates)
    {
        dim3 grid(12, MBIG / 256);
        conv_gemm_fp16_m256<<<grid, 256, SMEM_BYTES2>>>(xT, C_IN, 11, MBIG, KX / 64, KX, wx, pm);
    }
    // 8. sequential main recurrence: t=0 gate-only, then fused h-GEMM+gates
    gate0_kernel<<<(MSTEP * MEM_SZ + 255) / 256, 256>>>(b_fi, b_c, b_o);
    for (int t = 1; t < T_STEPS; t++) {
        dim3 grid(8, (MSTEP + 127) / 128);
        h_gemm_gates<<<grid, 256, HSMEM>>>(t, b_fi, b_c, b_o);
    }
    // 9. final pooling + FC head
    final_kernel<<<B_SZ, MEM_SZ>>>(W_fc, b_fc, lp, fp);
}

// round 11
// speedup vs baseline: 1.0594x; 1.0594x over previous
#include <cuda_runtime.h>
#include <cuda_fp16.h>
#include <math.h>
#include <stdint.h>

// ---------------------------------------------------------------------------
// Problem dims
// ---------------------------------------------------------------------------
#define T_STEPS 16
#define B_SZ    32
#define C_IN    2048
#define MEM_SZ  512
#define N_CLS   8
#define C_CAM   1000
#define HW      49
#define PADHW   81
#define KX      (C_IN*9)          // 18432
#define KH      (MEM_SZ*9)        // 4608
#define WROW    ((C_IN+MEM_SZ)*9) // 23040
#define MBIG    (T_STEPS*B_SZ*HW) // 25088
#define MSTEP   (B_SZ*HW)         // 1568
#define TB      (T_STEPS*B_SZ)    // 512
#define NFUSED  (3*MEM_SZ)        // 1536
#define XROW    (PADHW*C_IN)
#define HROW    (PADHW*MEM_SZ)

// ---------------------------------------------------------------------------
// Static device scratch
// ---------------------------------------------------------------------------
__device__ __half g_xT[(size_t)TB * XROW];
__device__ __half g_hT[B_SZ * HROW];
__device__ __half g_wx[(size_t)3 * MEM_SZ * KX];
__device__ __half g_wh[(size_t)3 * MEM_SZ * KH];
__device__ float  g_wsx[3 * KX];
__device__ float  g_preSp[3 * 9 * MBIG];   // per-tap partials [g][tap][m]
__device__ float  g_preS0[MBIG];
__device__ float  g_preS1[MBIG];
__device__ float  g_preS2[MBIG];
__device__ float  g_attmap[MBIG];
__device__ float  g_s[MBIG];
__device__ float  g_pooled[TB * C_IN];
__device__ float  g_logits[TB * C_CAM];
__device__ float  g_preM[(size_t)MBIG * NFUSED];
__device__ float  g_cstate[MSTEP * MEM_SZ];

__constant__ int c_border[32] = {
    0,1,2,3,4,5,6,7,8,
    72,73,74,75,76,77,78,79,80,
    9,17, 18,26, 27,35, 36,44, 45,53, 54,62, 63,71
};

__device__ __forceinline__ float sigmoidf_(float x) { return 1.0f / (1.0f + expf(-x)); }

// ---------------------------------------------------------------------------
// Pad + transpose x -> channels-last fp16 xT, zero borders, compute pooled
// grid (TB, C_IN/32), 256 thr
// ---------------------------------------------------------------------------
__global__ void pad_xT_pool(const float* __restrict__ x) {
    __shared__ float tile[32][50];
    int tb = blockIdx.x, c0 = blockIdx.y * 32;
    int tid = threadIdx.x;
    for (int idx = tid; idx < 32 * HW; idx += 256) {
        int r = idx / HW, q = idx - HW * r;
        tile[r][q] = x[((size_t)tb * C_IN + c0 + r) * HW + q];
    }
    __syncthreads();
    for (int idx = tid; idx < HW * 32; idx += 256) {
        int q = idx >> 5, cl = idx & 31;
        int p = (q / 7 + 1) * 9 + (q % 7) + 1;
        g_xT[(size_t)tb * XROW + (size_t)p * C_IN + c0 + cl] = __float2half_rn(tile[cl][q]);
    }
    for (int idx = tid; idx < 1024; idx += 256) {
        int bp = idx >> 5, cl = idx & 31;
        g_xT[(size_t)tb * XROW + (size_t)c_border[bp] * C_IN + c0 + cl] = __float2half_rn(0.f);
    }
    if (tid < 32) {
        float s = 0.f;
        #pragma unroll
        for (int q = 0; q < HW; q++) s += tile[tid][q];
        g_pooled[tb * C_IN + c0 + tid] = s * (1.0f / 49.0f);
    }
}

// ---------------------------------------------------------------------------
// One kernel: reorder wx/wh/ws to (tap, c) fp16/fp32 + zero hT/cstate
// ---------------------------------------------------------------------------
__global__ void reorder_all(const float* __restrict__ W0, const float* __restrict__ W1,
                            const float* __restrict__ W2,
                            const float* __restrict__ Wsfi, const float* __restrict__ Wsc,
                            const float* __restrict__ Wso) {
    size_t i = (size_t)blockIdx.x * 256 + threadIdx.x;
    const size_t S1 = (size_t)3 * MEM_SZ * C_IN;
    const size_t S2 = S1 + (size_t)3 * MEM_SZ * MEM_SZ;
    const size_t S3 = S2 + (size_t)3 * C_IN;
    const size_t S4 = S3 + (size_t)B_SZ * HROW;
    const size_t S5 = S4 + (size_t)MSTEP * MEM_SZ;
    if (i < S1) {
        int c = (int)(i & (C_IN - 1));
        int r = (int)(i >> 11);
        int n = r & (MEM_SZ - 1);
        int gate = r >> 9;
        const float* W = (gate == 0) ? W0 : (gate == 1 ? W1 : W2);
        const float* src = W + (size_t)n * WROW + (size_t)c * 9;
        __half* dst = g_wx + ((size_t)gate * MEM_SZ + n) * KX + c;
        #pragma unroll
        for (int tap = 0; tap < 9; tap++) dst[(size_t)tap * C_IN] = __float2half_rn(src[tap]);
    } else if (i < S2) {
        size_t lin = i - S1;
        int c = (int)(lin & (MEM_SZ - 1));
        int r = (int)(lin >> 9);
        int n = r & (MEM_SZ - 1);
        int gate = r >> 9;
        const float* W = (gate == 0) ? W0 : (gate == 1 ? W1 : W2);
        const float* src = W + (size_t)n * WROW + (size_t)(C_IN + c) * 9;
        __half* dst = g_wh + ((size_t)gate * MEM_SZ + n) * KH + c;
        #pragma unroll
        for (int tap = 0; tap < 9; tap++) dst[(size_t)tap * MEM_SZ] = __float2half_rn(src[tap]);
    } else if (i < S3) {
        int lin = (int)(i - S2);
        int gate = lin >> 11, c = lin & (C_IN - 1);
        const float* W = (gate == 0) ? Wsfi : (gate == 1 ? Wsc : Wso);
        #pragma unroll
        for (int tap = 0; tap < 9; tap++)
            g_wsx[gate * KX + tap * C_IN + c] = W[c * 9 + tap];
    } else if (i < S4) {
        g_hT[i - S3] = __float2half_rn(0.f);
    } else if (i < S5) {
        g_cstate[i - S4] = 0.f;
    }
}

// ---------------------------------------------------------------------------
// CAM logits as a tiled fp32 GEMM: logits[512,1000] = pooled @ W_cam^T
// ---------------------------------------------------------------------------
__global__ __launch_bounds__(256) void logits_gemm(const float* __restrict__ W_cam) {
    __shared__ float As[16][65];
    __shared__ float Bs[16][65];
    int j0 = blockIdx.x * 64, t0 = blockIdx.y * 64;
    int tid = threadIdx.x;
    int tx = tid & 15, ty = tid >> 4;
    float acc[4][4] = {};
    for (int k0 = 0; k0 < C_IN; k0 += 16) {
        #pragma unroll
        for (int r = 0; r < 4; r++) {
            int lin = tid + 256 * r;
            int m = lin >> 4, kk = lin & 15;
            As[kk][m] = g_pooled[(t0 + m) * C_IN + k0 + kk];
            int j = j0 + m;
            Bs[kk][m] = (j < C_CAM) ? W_cam[(size_t)j * C_IN + k0 + kk] : 0.f;
        }
        __syncthreads();
        #pragma unroll
        for (int kk = 0; kk < 16; kk++) {
            float a[4], b[4];
            #pragma unroll
            for (int u = 0; u < 4; u++) a[u] = As[kk][ty * 4 + u];
            #pragma unroll
            for (int u = 0; u < 4; u++) b[u] = Bs[kk][tx * 4 + u];
            #pragma unroll
            for (int u = 0; u < 4; u++)
                #pragma unroll
                for (int v = 0; v < 4; v++) acc[u][v] += a[u] * b[v];
        }
        __syncthreads();
    }
    #pragma unroll
    for (int u = 0; u < 4; u++)
        #pragma unroll
        for (int v = 0; v < 4; v++) {
            int j = j0 + tx * 4 + v;
            if (j < C_CAM)
                g_logits[(t0 + ty * 4 + u) * C_CAM + j] = acc[u][v];
        }
}

// ---------------------------------------------------------------------------
// Per-tb: argmax(logits) + CAM (lane=hw, coalesced fp32) + softmax -> attmap
// grid TB, 256 thr
// ---------------------------------------------------------------------------
__global__ __launch_bounds__(256) void cam_soft(const float* __restrict__ x,
                                                const float* __restrict__ W_cam) {
    int tb = blockIdx.x, tid = threadIdx.x;
    __shared__ float red[256];
    __shared__ int   redi[256];
    __shared__ float part[4][64];

    // ---- argmax over logits ----
    float best = -INFINITY; int bi = 0;
    for (int j = tid; j < C_CAM; j += 256) {
        float v = g_logits[tb * C_CAM + j];
        if (v > best) { best = v; bi = j; }
    }
    red[tid] = best; redi[tid] = bi; __syncthreads();
    for (int s = 128; s > 0; s >>= 1) {
        if (tid < s) {
            float v2 = red[tid + s]; int i2 = redi[tid + s];
            if (v2 > red[tid] || (v2 == red[tid] && i2 < redi[tid])) { red[tid] = v2; redi[tid] = i2; }
        }
        __syncthreads();
    }
    int cls = redi[0];
    __syncthreads();

    // ---- CAM: thread = (grp, hwl); coalesced x reads (consecutive hw) ----
    const float* wsel = W_cam + (size_t)cls * C_IN;
    const float* xb = x + (size_t)tb * C_IN * HW;
    int hwl = tid & 63, grp = tid >> 6;
    float acc = 0.f;
    if (hwl < HW) {
        for (int c = grp; c < C_IN; c += 4)
            acc += wsel[c] * xb[(size_t)c * HW + hwl];
    }
    part[grp][hwl] = acc;
    __syncthreads();
    float camv = 0.f;
    if (tid < HW) camv = part[0][tid] + part[1][tid] + part[2][tid] + part[3][tid];

    // ---- softmax -> attmap ----
    red[tid] = (tid < HW) ? camv : -INFINITY; __syncthreads();
    for (int s = 128; s > 0; s >>= 1) { if (tid < s) red[tid] = fmaxf(red[tid], red[tid + s]); __syncthreads(); }
    float mx = red[0]; __syncthreads();
    float e = (tid < HW) ? expf(camv - mx) : 0.f;
    red[tid] = e; __syncthreads();
    for (int s = 128; s > 0; s >>= 1) { if (tid < s) red[tid] += red[tid + s]; __syncthreads(); }
    if (tid < HW) g_attmap[tb * HW + tid] = e / red[0];
}

// ---------------------------------------------------------------------------
// preS per-tap partials: grid (TB, 9), 256 thr. No serial tap loop.
// Writes g_preSp[g][tap][m]; deterministic (no atomics).
// ---------------------------------------------------------------------------
__global__ __launch_bounds__(256) void preS_tap() {
    int tb = blockIdx.x, tap = blockIdx.y;
    int tid = threadIdx.x;
    int wid = tid >> 5, lane = tid & 31;
    __shared__ float ws[3 * C_IN];   // 24KB
    for (int idx = tid; idx < 3 * C_IN; idx += 256) {
        int g = idx >> 11, c = idx & (C_IN - 1);
        ws[idx] = g_wsx[g * KX + tap * C_IN + c];
    }
    __syncthreads();
    int dr = tap / 3, dc = tap - 3 * dr;
    const __half* xb = g_xT + (size_t)tb * XROW;
    #pragma unroll
    for (int j = 0; j < 7; j++) {
        int hw = wid + 8 * j;
        if (hw >= HW) break;
        int hh = hw / 7, wwp = hw - 7 * hh;
        const __half* xr = xb + (size_t)((hh + dr) * 9 + wwp + dc) * C_IN;
        float a0 = 0.f, a1 = 0.f, a2 = 0.f;
        for (int c = lane; c < C_IN; c += 32) {
            float v = __half2float(xr[c]);
            a0 += v * ws[c];
            a1 += v * ws[C_IN + c];
            a2 += v * ws[2 * C_IN + c];
        }
        #pragma unroll
        for (int o = 16; o > 0; o >>= 1) {
            a0 += __shfl_down_sync(0xffffffffu, a0, o);
            a1 += __shfl_down_sync(0xffffffffu, a1, o);
            a2 += __shfl_down_sync(0xffffffffu, a2, o);
        }
        if (lane == 0) {
            int m = tb * HW + hw;
            g_preSp[tap * MBIG + m]                = a0;
            g_preSp[(9 + tap) * MBIG + m]          = a1;
            g_preSp[(18 + tap) * MBIG + m]         = a2;
        }
    }
}

// ---------------------------------------------------------------------------
// Reduce 9 tap-partials -> preS0/1/2
// ---------------------------------------------------------------------------
__global__ void preS_reduce() {
    int m = blockIdx.x * 256 + threadIdx.x;
    if (m >= MBIG) return;
    float a0 = 0.f, a1 = 0.f, a2 = 0.f;
    #pragma unroll
    for (int tap = 0; tap < 9; tap++) {
        a0 += g_preSp[tap * MBIG + m];
        a1 += g_preSp[(9 + tap) * MBIG + m];
        a2 += g_preSp[(18 + tap) * MBIG + m];
    }
    g_preS0[m] = a0; g_preS1[m] = a1; g_preS2[m] = a2;
}

// ---------------------------------------------------------------------------
// Fused attention recurrence (16 steps, state in smem)
// ---------------------------------------------------------------------------
__global__ void att_fused(const float* __restrict__ Wfi, const float* __restrict__ Wc,
                          const float* __restrict__ Wo,
                          const float* __restrict__ bfi, const float* __restrict__ bc,
                          const float* __restrict__ bo) {
    int b = blockIdx.x, tid = threadIdx.x;
    __shared__ float ap[HW], av[HW], csh[HW], red[64];
    if (tid < HW) { ap[tid] = 0.f; csh[tid] = 0.f; }
    __syncthreads();
    for (int t = 0; t < T_STEPS; t++) {
        if (tid < HW) {
            int h = tid / 7, w = tid % 7;
            float efi = 0.f, ec = 0.f, eo = 0.f;
            #pragma unroll
            for (int kh = 0; kh < 3; kh++)
                #pragma unroll
                for (int kw = 0; kw < 3; kw++) {
                    int hh = h + kh - 1, ww = w + kw - 1;
                    if (hh >= 0 && hh < 7 && ww >= 0 && ww < 7) {
                        float aval = ap[hh * 7 + ww];
                        int off = KX + kh * 3 + kw;
                        efi += aval * Wfi[off];
                        ec  += aval * Wc[off];
                        eo  += aval * Wo[off];
                    }
                }
            int base = (t * B_SZ + b) * HW + tid;
            float fi = sigmoidf_(g_preS0[base] + efi + bfi[0]);
            float o  = sigmoidf_(g_preS2[base] + eo + bo[0]);
            float cc = tanhf(g_preS1[base] + ec + bc[0]);
            float cs = fi * csh[tid] + (1.0f - fi) * cc;
            csh[tid] = cs;
            av[tid] = o * tanhf(cs) * g_attmap[base];
        }
        __syncthreads();
        float m = (tid < HW) ? av[tid] : -INFINITY;
        red[tid] = m; __syncthreads();
        for (int s = 32; s > 0; s >>= 1) { if (tid < s) red[tid] = fmaxf(red[tid], red[tid + s]); __syncthreads(); }
        float mx = red[0]; __syncthreads();
        float e = (tid < HW) ? expf(av[tid] - mx) : 0.f;
        red[tid] = e; __syncthreads();
        for (int s = 32; s > 0; s >>= 1) { if (tid < s) red[tid] += red[tid + s]; __syncthreads(); }
        if (tid < HW) {
            g_s[(t * B_SZ + b) * HW + tid] = e / red[0];
            ap[tid] = av[tid];
        }
        __syncthreads();
    }
}

// ---------------------------------------------------------------------------
// x_att scaling (coalesced over c), fp16 in/out
// ---------------------------------------------------------------------------
__global__ void scale_x() {
    size_t lin = (size_t)blockIdx.x * 256 + threadIdx.x;
    if (lin >= (size_t)TB * HW * C_IN) return;
    int c  = lin & (C_IN - 1);
    int rc = (int)(lin >> 11);
    int tb = rc / HW, hw = rc - HW * tb;
    float sc = g_s[rc];
    int p = (hw / 7 + 1) * 9 + (hw % 7) + 1;
    size_t a = (size_t)tb * XROW + (size_t)p * C_IN + c;
    g_xT[a] = __float2half_rn(__half2float(g_xT[a]) * sc);
}

// ---------------------------------------------------------------------------
// FP16 implicit GEMM, 256(M)x128(N)x64(K), 8 warps (4m x 2n), warp 64x64.
// ---------------------------------------------------------------------------
#define STGB2 49152
#define PIPE 3

__global__ __launch_bounds__(256, 1) void conv_gemm_fp16_m256(
    const __half* __restrict__ Apad, int Crow, int cshift, int M, int KT, int Kfull,
    const __half* __restrict__ Wbase, float* __restrict__ Out)
{
    extern __shared__ char smc[];
    const int tid  = threadIdx.x;
    const int m0   = blockIdx.y * 256;
    const int gate = blockIdx.x >> 2;
    const int n0in = (blockIdx.x & 3) * 128;
    const __half* Wg = Wbase + ((size_t)gate * MEM_SZ + n0in) * Kfull;

    const int rlo = tid >> 3;
    const int kq  = (tid & 7) * 8;
    const int stChunk = ((tid & 7) ^ (rlo & 7)) << 4;

    size_t rowoff[8]; int asz[8];
    #pragma unroll
    for (int i = 0; i < 8; i++) {
        int m = m0 + rlo + 32 * i;
        if (m < M) {
            int tb = m / HW, hw = m - HW * tb;
            rowoff[i] = ((size_t)tb * PADHW + (size_t)((hw / 7) * 9 + hw % 7)) * Crow;
            asz[i] = 16;
        } else { rowoff[i] = 0; asz[i] = 0; }
    }

    const int lane = tid & 31;
    const int wid  = tid >> 5;
    const int g    = lane >> 2;
    const int cq   = lane & 3;
    const int wmB  = (wid & 3) * 64;
    const int wnB  = (wid >> 2) * 64;

    float acc[4][8][4];
    #pragma unroll
    for (int a = 0; a < 4; a++)
        #pragma unroll
        for (int b = 0; b < 8; b++)
            #pragma unroll
            for (int c = 0; c < 4; c++) acc[a][b][c] = 0.f;

    auto issue = [&](int s, int kt) {
        char* As_ = smc + s * STGB2;
        char* Bs_ = As_ + 32768;
        uint32_t aB = (uint32_t)__cvta_generic_to_shared(As_);
        uint32_t bB = (uint32_t)__cvta_generic_to_shared(Bs_);
        int k0  = kt * 64;
        int tap = k0 >> cshift;
        int c0  = k0 & (Crow - 1);
        int dr  = tap / 3, dc = tap - 3 * dr;
        size_t poff = (size_t)(dr * 9 + dc) * Crow + c0 + kq;
        #pragma unroll
        for (int i = 0; i < 8; i++) {
            const __half* src = Apad + rowoff[i] + poff;
            uint32_t dst = aB + (uint32_t)((rlo + 32 * i) * 128 + stChunk);
            asm volatile("cp.async.cg.shared.global [%0], [%1], 16, %2;\n"
                         :: "r"(dst), "l"(src), "r"(asz[i]));
        }
        #pragma unroll
        for (int i = 0; i < 4; i++) {
            int nl = rlo + 32 * i;
            const __half* src = Wg + (size_t)nl * Kfull + k0 + kq;
            uint32_t dst = bB + (uint32_t)(nl * 128 + stChunk);
            asm volatile("cp.async.cg.shared.global [%0], [%1], 16;\n"
                         :: "r"(dst), "l"(src));
        }
        asm volatile("cp.async.commit_group;\n");
    };

    #pragma unroll
    for (int s = 0; s < PIPE - 1; s++)
        if (s < KT) issue(s, s);

    for (int kt = 0; kt < KT; kt++) {
        if (kt + 1 < KT) asm volatile("cp.async.wait_group 1;\n" ::: "memory");
        else             asm volatile("cp.async.wait_group 0;\n" ::: "memory");
        __syncthreads();
        if (kt + PIPE - 1 < KT) issue((kt + PIPE - 1) % PIPE, kt + PIPE - 1);

        const char* As_ = smc + (kt % PIPE) * STGB2;
        const char* Bs_ = As_ + 32768;

        #pragma unroll
        for (int ks = 0; ks < 4; ks++) {
            const int ch0 = (((2 * ks)     ^ g) << 4) + 4 * cq;
            const int ch1 = (((2 * ks + 1) ^ g) << 4) + 4 * cq;
            unsigned af[4][4], bf[8][2];
            #pragma unroll
            for (int mt = 0; mt < 4; mt++) {
                const char* r0p = As_ + (wmB + mt * 16 + g) * 128;
                const char* r1p = r0p + 8 * 128;
                af[mt][0] = *(const uint32_t*)(r0p + ch0);
                af[mt][1] = *(const uint32_t*)(r1p + ch0);
                af[mt][2] = *(const uint32_t*)(r0p + ch1);
                af[mt][3] = *(const uint32_t*)(r1p + ch1);
            }
            #pragma unroll
            for (int nt = 0; nt < 8; nt++) {
                const char* np = Bs_ + (wnB + nt * 8 + g) * 128;
                bf[nt][0] = *(const uint32_t*)(np + ch0);
                bf[nt][1] = *(const uint32_t*)(np + ch1);
            }
            #pragma unroll
            for (int mt = 0; mt < 4; mt++)
                #pragma unroll
                for (int nt = 0; nt < 8; nt++) {
                    asm volatile(
                        "mma.sync.aligned.m16n8k16.row.col.f32.f16.f16.f32 "
                        "{%0,%1,%2,%3}, {%4,%5,%6,%7}, {%8,%9}, {%0,%1,%2,%3};\n"
                        : "+f"(acc[mt][nt][0]), "+f"(acc[mt][nt][1]),
                          "+f"(acc[mt][nt][2]), "+f"(acc[mt][nt][3])
                        : "r"(af[mt][0]), "r"(af[mt][1]), "r"(af[mt][2]), "r"(af[mt][3]),
                          "r"(bf[nt][0]), "r"(bf[nt][1]));
                }
        }
        __syncthreads();
    }

    const size_t colBase = (size_t)(gate * MEM_SZ + n0in);
    #pragma unroll
    for (int mt = 0; mt < 4; mt++) {
        int r0 = m0 + wmB + mt * 16 + g;
        #pragma unroll
        for (int nt = 0; nt < 8; nt++) {
            size_t co = colBase + wnB + nt * 8 + cq * 2;
            if (r0 < M) {
                float2 v = make_float2(acc[mt][nt][0], acc[mt][nt][1]);
                *(float2*)&Out[(size_t)r0 * NFUSED + co] = v;
            }
            if (r0 + 8 < M) {
                float2 v = make_float2(acc[mt][nt][2], acc[mt][nt][3]);
                *(float2*)&Out[(size_t)(r0 + 8) * NFUSED + co] = v;
            }
        }
    }
}

// ---------------------------------------------------------------------------
// h-chain: fused h-GEMM (128m x 192n-eff [64n x 3 gates] x 64k) + gate epilogue
// ---------------------------------------------------------------------------
#define HST   40960
#define HSMEM (PIPE * HST)
#define OST   196

__global__ __launch_bounds__(256, 1) void h_gemm_gates(
    int t, const float* __restrict__ bfi, const float* __restrict__ bc,
    const float* __restrict__ bo)
{
    extern __shared__ char smc[];
    const int tid = threadIdx.x;
    const int nb  = blockIdx.x;
    const int m0  = blockIdx.y * 128;

    const int rlo = tid >> 3;
    const int kq  = (tid & 7) * 8;
    const int stChunk = ((tid & 7) ^ (rlo & 7)) << 4;

    size_t rowoff[4]; int asz[4];
    #pragma unroll
    for (int i = 0; i < 4; i++) {
        int m = m0 + rlo + 32 * i;
        if (m < MSTEP) {
            int b = m / HW, hw = m - HW * b;
            rowoff[i] = ((size_t)b * PADHW + (size_t)((hw / 7) * 9 + hw % 7)) * MEM_SZ;
            asz[i] = 16;
        } else { rowoff[i] = 0; asz[i] = 0; }
    }
    const __half* bsrc[6];
    #pragma unroll
    for (int i = 0; i < 6; i++) {
        int j = rlo + 32 * i;
        int gate = j >> 6, jj = j & 63;
        bsrc[i] = g_wh + ((size_t)(gate * MEM_SZ + nb * 64 + jj)) * KH;
    }

    const int lane = tid & 31;
    const int wid  = tid >> 5;
    const int g    = lane >> 2;
    const int cq   = lane & 3;
    const int wmB  = (wid & 1) * 64;
    const int wnB  = (wid >> 1) * 48;

    float acc[4][6][4];
    #pragma unroll
    for (int a = 0; a < 4; a++)
        #pragma unroll
        for (int b = 0; b < 6; b++)
            #pragma unroll
            for (int c = 0; c < 4; c++) acc[a][b][c] = 0.f;

    auto issue = [&](int s, int kt) {
        char* As_ = smc + s * HST;
        char* Bs_ = As_ + 16384;
        uint32_t aB = (uint32_t)__cvta_generic_to_shared(As_);
        uint32_t bB = (uint32_t)__cvta_generic_to_shared(Bs_);
        int k0  = kt * 64;
        int tap = k0 >> 9;
        int c0  = k0 & (MEM_SZ - 1);
        int dr  = tap / 3, dc = tap - 3 * dr;
        size_t poff = (size_t)(dr * 9 + dc) * MEM_SZ + c0 + kq;
        #pragma unroll
        for (int i = 0; i < 4; i++) {
            const __half* src = g_hT + rowoff[i] + poff;
            uint32_t dst = aB + (uint32_t)((rlo + 32 * i) * 128 + stChunk);
            asm volatile("cp.async.cg.shared.global [%0], [%1], 16, %2;\n"
                         :: "r"(dst), "l"(src), "r"(asz[i]));
        }
        #pragma unroll
        for (int i = 0; i < 6; i++) {
            const __half* src = bsrc[i] + k0 + kq;
            uint32_t dst = bB + (uint32_t)((rlo + 32 * i) * 128 + stChunk);
            asm volatile("cp.async.cg.shared.global [%0], [%1], 16;\n"
                         :: "r"(dst), "l"(src));
        }
        asm volatile("cp.async.commit_group;\n");
    };

    const int KT = KH / 64;
    #pragma unroll
    for (int s = 0; s < PIPE - 1; s++) issue(s, s);

    for (int kt = 0; kt < KT; kt++) {
        if (kt + 1 < KT) asm volatile("cp.async.wait_group 1;\n" ::: "memory");
        else             asm volatile("cp.async.wait_group 0;\n" ::: "memory");
        __syncthreads();
        if (kt + PIPE - 1 < KT) issue((kt + PIPE - 1) % PIPE, kt + PIPE - 1);

        const char* As_ = smc + (kt % PIPE) * HST;
        const char* Bs_ = As_ + 16384;

        #pragma unroll
        for (int ks = 0; ks < 4; ks++) {
            const int ch0 = (((2 * ks)     ^ g) << 4) + 4 * cq;
            const int ch1 = (((2 * ks + 1) ^ g) << 4) + 4 * cq;
            unsigned af[4][4], bf[6][2];
            #pragma unroll
            for (int mt = 0; mt < 4; mt++) {
                const char* r0p = As_ + (wmB + mt * 16 + g) * 128;
                const char* r1p = r0p + 8 * 128;
                af[mt][0] = *(const uint32_t*)(r0p + ch0);
                af[mt][1] = *(const uint32_t*)(r1p + ch0);
                af[mt][2] = *(const uint32_t*)(r0p + ch1);
                af[mt][3] = *(const uint32_t*)(r1p + ch1);
            }
            #pragma unroll
            for (int nt = 0; nt < 6; nt++) {
                const char* np = Bs_ + (wnB + nt * 8 + g) * 128;
                bf[nt][0] = *(const uint32_t*)(np + ch0);
                bf[nt][1] = *(const uint32_t*)(np + ch1);
            }
            #pragma unroll
            for (int mt = 0; mt < 4; mt++)
                #pragma unroll
                for (int nt = 0; nt < 6; nt++) {
                    asm volatile(
                        "mma.sync.aligned.m16n8k16.row.col.f32.f16.f16.f32 "
                        "{%0,%1,%2,%3}, {%4,%5,%6,%7}, {%8,%9}, {%0,%1,%2,%3};\n"
                        : "+f"(acc[mt][nt][0]), "+f"(acc[mt][nt][1]),
                          "+f"(acc[mt][nt][2]), "+f"(acc[mt][nt][3])
                        : "r"(af[mt][0]), "r"(af[mt][1]), "r"(af[mt][2]), "r"(af[mt][3]),
                          "r"(bf[nt][0]), "r"(bf[nt][1]));
                }
        }
        __syncthreads();
    }

    // ---- epilogue: stash GEMM tile in smem, then fused gate update ----
    float* Osm = (float*)smc;
    #pragma unroll
    for (int mt = 0; mt < 4; mt++) {
        int r = wmB + mt * 16 + g;
        #pragma unroll
        for (int nt = 0; nt < 6; nt++) {
            int co = wnB + nt * 8 + cq * 2;
            *(float2*)&Osm[r * OST + co]       = make_float2(acc[mt][nt][0], acc[mt][nt][1]);
            *(float2*)&Osm[(r + 8) * OST + co] = make_float2(acc[mt][nt][2], acc[mt][nt][3]);
        }
    }
    __syncthreads();

    #pragma unroll
    for (int it = 0; it < 32; it++) {
        int idx = tid + 256 * it;
        int ml = idx >> 6, nl = idx & 63;
        int m = m0 + ml;
        if (m >= MSTEP) continue;
        float g0 = Osm[ml * OST + nl];
        float g1 = Osm[ml * OST + 64 + nl];
        float g2 = Osm[ml * OST + 128 + nl];
        int n = nb * 64 + nl;
        size_t pOff = ((size_t)(t * MSTEP + m)) * NFUSED;
        float pfi = g_preM[pOff + n]        + g0 + bfi[n];
        float pc  = g_preM[pOff + 512 + n]  + g1 + bc[n];
        float po  = g_preM[pOff + 1024 + n] + g2 + bo[n];
        float fi = sigmoidf_(pfi);
        float o  = sigmoidf_(po);
        int lin = m * MEM_SZ + n;
        float cn = fi * g_cstate[lin] + (1.0f - fi) * tanhf(pc);
        g_cstate[lin] = cn;
        float h = o * tanhf(cn);
        int b = m / HW, hw = m - HW * b;
        int p = (hw / 7 + 1) * 9 + (hw % 7) + 1;
        g_hT[(size_t)b * HROW + (size_t)p * MEM_SZ + n] = __float2half_rn(h);
    }
}

// ---------------------------------------------------------------------------
// Step 0 gate update (h = 0, cstate = 0 -> no h-GEMM needed)
// ---------------------------------------------------------------------------
__global__ void gate0_kernel(const float* __restrict__ bfi,
                             const float* __restrict__ bc, const float* __restrict__ bo) {
    int lin = blockIdx.x * 256 + threadIdx.x;
    if (lin >= MSTEP * MEM_SZ) return;
    int n = lin & (MEM_SZ - 1);
    int m = lin >> 9;
    int b = m / HW, hw = m - HW * b;
    size_t pOff = (size_t)m * NFUSED;
    float pfi = g_preM[pOff + n]        + bfi[n];
    float pc  = g_preM[pOff + 512 + n]  + bc[n];
    float po  = g_preM[pOff + 1024 + n] + bo[n];
    float fi = sigmoidf_(pfi);
    float o  = sigmoidf_(po);
    float cn = (1.0f - fi) * tanhf(pc);
    g_cstate[lin] = cn;
    float h = o * tanhf(cn);
    int p = (hw / 7 + 1) * 9 + (hw % 7) + 1;
    g_hT[(size_t)b * HROW + (size_t)p * MEM_SZ + n] = __float2half_rn(h);
}

// ---------------------------------------------------------------------------
// Final: feats = mean_hw(h); logits = feats @ W_fc^T + b_fc
// ---------------------------------------------------------------------------
__global__ void final_kernel(const float* __restrict__ W_fc, const float* __restrict__ b_fc,
                             float* __restrict__ logitsOut, float* __restrict__ featsOut) {
    int b = blockIdx.x, n = threadIdx.x;
    const __half* hb = &g_hT[(size_t)b * HROW];
    float s = 0.f;
    #pragma unroll
    for (int hh = 1; hh <= 7; hh++)
        #pragma unroll
        for (int ww = 1; ww <= 7; ww++) s += __half2float(hb[(size_t)(hh * 9 + ww) * MEM_SZ + n]);
    float f = s * (1.0f / 49.0f);
    __shared__ float fs[MEM_SZ];
    fs[n] = f;
    if (featsOut) featsOut[b * MEM_SZ + n] = f;
    __syncthreads();
    if (n < N_CLS && logitsOut) {
        float acc = b_fc[n];
        for (int k = 0; k < MEM_SZ; k++) acc += fs[k] * W_fc[n * MEM_SZ + k];
        logitsOut[b * N_CLS + n] = acc;
    }
}

// ---------------------------------------------------------------------------
// Host launcher
// ---------------------------------------------------------------------------
extern "C" void kernel_launch(void* const* d_in, const int* in_sizes, int n_in,
                              void* d_out, int out_size) {
    const float* x     = (const float*)d_in[0];
    const float* W_fi  = (const float*)d_in[1];
    const float* b_fi  = (const float*)d_in[2];
    const float* W_c   = (const float*)d_in[3];
    const float* b_c   = (const float*)d_in[4];
    const float* W_o   = (const float*)d_in[5];
    const float* b_o   = (const float*)d_in[6];
    const float* Ws_fi = (const float*)d_in[7];
    const float* bs_fi = (const float*)d_in[8];
    const float* Ws_c  = (const float*)d_in[9];
    const float* bs_c  = (const float*)d_in[10];
    const float* Ws_o  = (const float*)d_in[11];
    const float* bs_o  = (const float*)d_in[12];
    const float* W_cam = (const float*)d_in[13];
    const float* W_fc  = (const float*)d_in[14];
    const float* b_fc  = (const float*)d_in[15];

    __half* xT; cudaGetSymbolAddress((void**)&xT, g_xT);
    __half* wx; cudaGetSymbolAddress((void**)&wx, g_wx);
    float*  pm; cudaGetSymbolAddress((void**)&pm, g_preM);

    const int SMEM_BYTES2 = PIPE * STGB2;
    cudaFuncSetAttribute(conv_gemm_fp16_m256, cudaFuncAttributeMaxDynamicSharedMemorySize, SMEM_BYTES2);
    cudaFuncSetAttribute(h_gemm_gates, cudaFuncAttributeMaxDynamicSharedMemorySize, HSMEM);

    float* outF = (float*)d_out;
    float* lp = nullptr; float* fp = nullptr;
    if (out_size >= B_SZ * N_CLS + B_SZ * MEM_SZ) { lp = outF; fp = outF + B_SZ * N_CLS; }
    else if (out_size == B_SZ * MEM_SZ)           { fp = outF; }
    else                                          { lp = outF; }

    // 1. pad + transpose x (fp16, borders, pooled)
    {
        dim3 grid(TB, C_IN / 32);
        pad_xT_pool<<<grid, 256>>>(x);
    }
    // 2. reorder all weights + zero recurrent state
    {
        const size_t TOT = (size_t)3 * MEM_SZ * C_IN + (size_t)3 * MEM_SZ * MEM_SZ
                         + (size_t)3 * C_IN + (size_t)B_SZ * HROW + (size_t)MSTEP * MEM_SZ;
        reorder_all<<<(int)((TOT + 255) / 256), 256>>>(W_fi, W_c, W_o, Ws_fi, Ws_c, Ws_o);
    }
    // 3. CAM logits (tiled GEMM)
    {
        dim3 grid((C_CAM + 63) / 64, TB / 64);
        logits_gemm<<<grid, 256>>>(W_cam);
    }
    // 4. argmax + CAM map + softmax (per tb, coalesced)
    cam_soft<<<TB, 256>>>(x, W_cam);
    // 5. preS partials (tb x tap parallel) + reduce
    {
        dim3 grid(TB, 9);
        preS_tap<<<grid, 256>>>();
    }
    preS_reduce<<<(MBIG + 255) / 256, 256>>>();
    // 6. fused attention recurrence
    att_fused<<<B_SZ, 64>>>(Ws_fi, Ws_c, Ws_o, bs_fi, bs_c, bs_o);
    // 7. attention scaling
    scale_x<<<(int)(((size_t)TB * HW * C_IN + 255) / 256), 256>>>();
    // 8. giant parallel GEMM (x part, all t, 3 gates)
    {
        dim3 grid(12, MBIG / 256);
        conv_gemm_fp16_m256<<<grid, 256, SMEM_BYTES2>>>(xT, C_IN, 11, MBIG, KX / 64, KX, wx, pm);
    }
    // 9. sequential main recurrence: t=0 gate-only, then fused h-GEMM+gates
    gate0_kernel<<<(MSTEP * MEM_SZ + 255) / 256, 256>>>(b_fi, b_c, b_o);
    for (int t = 1; t < T_STEPS; t++) {
        dim3 grid(8, (MSTEP + 127) / 128);
        h_gemm_gates<<<grid, 256, HSMEM>>>(t, b_fi, b_c, b_o);
    }
    // 10. final pooling + FC head
    final_kernel<<<B_SZ, MEM_SZ>>>(W_fc, b_fc, lp, fp);
}

// round 12
// speedup vs baseline: 1.0808x; 1.0203x over previous
#include <cuda_runtime.h>
#include <cuda_fp16.h>
#include <math.h>
#include <stdint.h>

// ---------------------------------------------------------------------------
// Problem dims
// ---------------------------------------------------------------------------
#define T_STEPS 16
#define B_SZ    32
#define C_IN    2048
#define MEM_SZ  512
#define N_CLS   8
#define C_CAM   1000
#define HW      49
#define PADHW   81
#define KX      (C_IN*9)          // 18432
#define KH      (MEM_SZ*9)        // 4608
#define WROW    ((C_IN+MEM_SZ)*9) // 23040
#define MBIG    (T_STEPS*B_SZ*HW) // 25088
#define MSTEP   (B_SZ*HW)         // 1568
#define TB      (T_STEPS*B_SZ)    // 512
#define NFUSED  (3*MEM_SZ)        // 1536
#define XROW    (PADHW*C_IN)
#define HROW    (PADHW*MEM_SZ)

// ---------------------------------------------------------------------------
// Static device scratch
// ---------------------------------------------------------------------------
__device__ __half g_xT[(size_t)TB * XROW];
__device__ __half g_hT[B_SZ * HROW];
__device__ __half g_wx[(size_t)3 * MEM_SZ * KX];
__device__ __half g_wh[(size_t)3 * MEM_SZ * KH];
__device__ float  g_wsx[3 * KX];
__device__ float  g_preSp[3 * 9 * MBIG];   // per-tap partials [g][tap][m]
__device__ float  g_preS0[MBIG];
__device__ float  g_preS1[MBIG];
__device__ float  g_preS2[MBIG];
__device__ float  g_attmap[MBIG];
__device__ float  g_s[MBIG];
__device__ float  g_pooled[TB * C_IN];
__device__ float  g_logits[TB * C_CAM];
__device__ float  g_preM[(size_t)MBIG * NFUSED];
__device__ float  g_cstate[MSTEP * MEM_SZ];

__constant__ int c_border[32] = {
    0,1,2,3,4,5,6,7,8,
    72,73,74,75,76,77,78,79,80,
    9,17, 18,26, 27,35, 36,44, 45,53, 54,62, 63,71
};

__device__ __forceinline__ float sigmoidf_(float x) { return 1.0f / (1.0f + expf(-x)); }

// ---------------------------------------------------------------------------
// Pad + transpose x -> channels-last fp16 xT, zero borders, compute pooled
// ---------------------------------------------------------------------------
__global__ void pad_xT_pool(const float* __restrict__ x) {
    __shared__ float tile[32][50];
    int tb = blockIdx.x, c0 = blockIdx.y * 32;
    int tid = threadIdx.x;
    for (int idx = tid; idx < 32 * HW; idx += 256) {
        int r = idx / HW, q = idx - HW * r;
        tile[r][q] = x[((size_t)tb * C_IN + c0 + r) * HW + q];
    }
    __syncthreads();
    for (int idx = tid; idx < HW * 32; idx += 256) {
        int q = idx >> 5, cl = idx & 31;
        int p = (q / 7 + 1) * 9 + (q % 7) + 1;
        g_xT[(size_t)tb * XROW + (size_t)p * C_IN + c0 + cl] = __float2half_rn(tile[cl][q]);
    }
    for (int idx = tid; idx < 1024; idx += 256) {
        int bp = idx >> 5, cl = idx & 31;
        g_xT[(size_t)tb * XROW + (size_t)c_border[bp] * C_IN + c0 + cl] = __float2half_rn(0.f);
    }
    if (tid < 32) {
        float s = 0.f;
        #pragma unroll
        for (int q = 0; q < HW; q++) s += tile[tid][q];
        g_pooled[tb * C_IN + c0 + tid] = s * (1.0f / 49.0f);
    }
}

// ---------------------------------------------------------------------------
// One kernel: reorder wx/wh/ws to (tap, c) fp16/fp32 + zero hT/cstate
// ---------------------------------------------------------------------------
__global__ void reorder_all(const float* __restrict__ W0, const float* __restrict__ W1,
                            const float* __restrict__ W2,
                            const float* __restrict__ Wsfi, const float* __restrict__ Wsc,
                            const float* __restrict__ Wso) {
    size_t i = (size_t)blockIdx.x * 256 + threadIdx.x;
    const size_t S1 = (size_t)3 * MEM_SZ * C_IN;
    const size_t S2 = S1 + (size_t)3 * MEM_SZ * MEM_SZ;
    const size_t S3 = S2 + (size_t)3 * C_IN;
    const size_t S4 = S3 + (size_t)B_SZ * HROW;
    const size_t S5 = S4 + (size_t)MSTEP * MEM_SZ;
    if (i < S1) {
        int c = (int)(i & (C_IN - 1));
        int r = (int)(i >> 11);
        int n = r & (MEM_SZ - 1);
        int gate = r >> 9;
        const float* W = (gate == 0) ? W0 : (gate == 1 ? W1 : W2);
        const float* src = W + (size_t)n * WROW + (size_t)c * 9;
        __half* dst = g_wx + ((size_t)gate * MEM_SZ + n) * KX + c;
        #pragma unroll
        for (int tap = 0; tap < 9; tap++) dst[(size_t)tap * C_IN] = __float2half_rn(src[tap]);
    } else if (i < S2) {
        size_t lin = i - S1;
        int c = (int)(lin & (MEM_SZ - 1));
        int r = (int)(lin >> 9);
        int n = r & (MEM_SZ - 1);
        int gate = r >> 9;
        const float* W = (gate == 0) ? W0 : (gate == 1 ? W1 : W2);
        const float* src = W + (size_t)n * WROW + (size_t)(C_IN + c) * 9;
        __half* dst = g_wh + ((size_t)gate * MEM_SZ + n) * KH + c;
        #pragma unroll
        for (int tap = 0; tap < 9; tap++) dst[(size_t)tap * MEM_SZ] = __float2half_rn(src[tap]);
    } else if (i < S3) {
        int lin = (int)(i - S2);
        int gate = lin >> 11, c = lin & (C_IN - 1);
        const float* W = (gate == 0) ? Wsfi : (gate == 1 ? Wsc : Wso);
        #pragma unroll
        for (int tap = 0; tap < 9; tap++)
            g_wsx[gate * KX + tap * C_IN + c] = W[c * 9 + tap];
    } else if (i < S4) {
        g_hT[i - S3] = __float2half_rn(0.f);
    } else if (i < S5) {
        g_cstate[i - S4] = 0.f;
    }
}

// ---------------------------------------------------------------------------
// CAM logits as a tiled fp32 GEMM: logits[512,1000] = pooled @ W_cam^T
// ---------------------------------------------------------------------------
__global__ __launch_bounds__(256) void logits_gemm(const float* __restrict__ W_cam) {
    __shared__ float As[16][65];
    __shared__ float Bs[16][65];
    int j0 = blockIdx.x * 64, t0 = blockIdx.y * 64;
    int tid = threadIdx.x;
    int tx = tid & 15, ty = tid >> 4;
    float acc[4][4] = {};
    for (int k0 = 0; k0 < C_IN; k0 += 16) {
        #pragma unroll
        for (int r = 0; r < 4; r++) {
            int lin = tid + 256 * r;
            int m = lin >> 4, kk = lin & 15;
            As[kk][m] = g_pooled[(t0 + m) * C_IN + k0 + kk];
            int j = j0 + m;
            Bs[kk][m] = (j < C_CAM) ? W_cam[(size_t)j * C_IN + k0 + kk] : 0.f;
        }
        __syncthreads();
        #pragma unroll
        for (int kk = 0; kk < 16; kk++) {
            float a[4], b[4];
            #pragma unroll
            for (int u = 0; u < 4; u++) a[u] = As[kk][ty * 4 + u];
            #pragma unroll
            for (int u = 0; u < 4; u++) b[u] = Bs[kk][tx * 4 + u];
            #pragma unroll
            for (int u = 0; u < 4; u++)
                #pragma unroll
                for (int v = 0; v < 4; v++) acc[u][v] += a[u] * b[v];
        }
        __syncthreads();
    }
    #pragma unroll
    for (int u = 0; u < 4; u++)
        #pragma unroll
        for (int v = 0; v < 4; v++) {
            int j = j0 + tx * 4 + v;
            if (j < C_CAM)
                g_logits[(t0 + ty * 4 + u) * C_CAM + j] = acc[u][v];
        }
}

// ---------------------------------------------------------------------------
// Per-tb: argmax(logits) + CAM (coalesced) + softmax -> attmap
// ---------------------------------------------------------------------------
__global__ __launch_bounds__(256) void cam_soft(const float* __restrict__ x,
                                                const float* __restrict__ W_cam) {
    int tb = blockIdx.x, tid = threadIdx.x;
    __shared__ float red[256];
    __shared__ int   redi[256];
    __shared__ float part[4][64];

    float best = -INFINITY; int bi = 0;
    for (int j = tid; j < C_CAM; j += 256) {
        float v = g_logits[tb * C_CAM + j];
        if (v > best) { best = v; bi = j; }
    }
    red[tid] = best; redi[tid] = bi; __syncthreads();
    for (int s = 128; s > 0; s >>= 1) {
        if (tid < s) {
            float v2 = red[tid + s]; int i2 = redi[tid + s];
            if (v2 > red[tid] || (v2 == red[tid] && i2 < redi[tid])) { red[tid] = v2; redi[tid] = i2; }
        }
        __syncthreads();
    }
    int cls = redi[0];
    __syncthreads();

    const float* wsel = W_cam + (size_t)cls * C_IN;
    const float* xb = x + (size_t)tb * C_IN * HW;
    int hwl = tid & 63, grp = tid >> 6;
    float acc = 0.f;
    if (hwl < HW) {
        for (int c = grp; c < C_IN; c += 4)
            acc += wsel[c] * xb[(size_t)c * HW + hwl];
    }
    part[grp][hwl] = acc;
    __syncthreads();
    float camv = 0.f;
    if (tid < HW) camv = part[0][tid] + part[1][tid] + part[2][tid] + part[3][tid];

    red[tid] = (tid < HW) ? camv : -INFINITY; __syncthreads();
    for (int s = 128; s > 0; s >>= 1) { if (tid < s) red[tid] = fmaxf(red[tid], red[tid + s]); __syncthreads(); }
    float mx = red[0]; __syncthreads();
    float e = (tid < HW) ? expf(camv - mx) : 0.f;
    red[tid] = e; __syncthreads();
    for (int s = 128; s > 0; s >>= 1) { if (tid < s) red[tid] += red[tid + s]; __syncthreads(); }
    if (tid < HW) g_attmap[tb * HW + tid] = e / red[0];
}

// ---------------------------------------------------------------------------
// preS per-tap partials: grid (TB, 9)
// ---------------------------------------------------------------------------
__global__ __launch_bounds__(256) void preS_tap() {
    int tb = blockIdx.x, tap = blockIdx.y;
    int tid = threadIdx.x;
    int wid = tid >> 5, lane = tid & 31;
    __shared__ float ws[3 * C_IN];
    for (int idx = tid; idx < 3 * C_IN; idx += 256) {
        int g = idx >> 11, c = idx & (C_IN - 1);
        ws[idx] = g_wsx[g * KX + tap * C_IN + c];
    }
    __syncthreads();
    int dr = tap / 3, dc = tap - 3 * dr;
    const __half* xb = g_xT + (size_t)tb * XROW;
    #pragma unroll
    for (int j = 0; j < 7; j++) {
        int hw = wid + 8 * j;
        if (hw >= HW) break;
        int hh = hw / 7, wwp = hw - 7 * hh;
        const __half* xr = xb + (size_t)((hh + dr) * 9 + wwp + dc) * C_IN;
        float a0 = 0.f, a1 = 0.f, a2 = 0.f;
        for (int c = lane; c < C_IN; c += 32) {
            float v = __half2float(xr[c]);
            a0 += v * ws[c];
            a1 += v * ws[C_IN + c];
            a2 += v * ws[2 * C_IN + c];
        }
        #pragma unroll
        for (int o = 16; o > 0; o >>= 1) {
            a0 += __shfl_down_sync(0xffffffffu, a0, o);
            a1 += __shfl_down_sync(0xffffffffu, a1, o);
            a2 += __shfl_down_sync(0xffffffffu, a2, o);
        }
        if (lane == 0) {
            int m = tb * HW + hw;
            g_preSp[tap * MBIG + m]        = a0;
            g_preSp[(9 + tap) * MBIG + m]  = a1;
            g_preSp[(18 + tap) * MBIG + m] = a2;
        }
    }
}

__global__ void preS_reduce() {
    int m = blockIdx.x * 256 + threadIdx.x;
    if (m >= MBIG) return;
    float a0 = 0.f, a1 = 0.f, a2 = 0.f;
    #pragma unroll
    for (int tap = 0; tap < 9; tap++) {
        a0 += g_preSp[tap * MBIG + m];
        a1 += g_preSp[(9 + tap) * MBIG + m];
        a2 += g_preSp[(18 + tap) * MBIG + m];
    }
    g_preS0[m] = a0; g_preS1[m] = a1; g_preS2[m] = a2;
}

// ---------------------------------------------------------------------------
// Fused attention recurrence (16 steps, state in smem)
// ---------------------------------------------------------------------------
__global__ void att_fused(const float* __restrict__ Wfi, const float* __restrict__ Wc,
                          const float* __restrict__ Wo,
                          const float* __restrict__ bfi, const float* __restrict__ bc,
                          const float* __restrict__ bo) {
    int b = blockIdx.x, tid = threadIdx.x;
    __shared__ float ap[HW], av[HW], csh[HW], red[64];
    if (tid < HW) { ap[tid] = 0.f; csh[tid] = 0.f; }
    __syncthreads();
    for (int t = 0; t < T_STEPS; t++) {
        if (tid < HW) {
            int h = tid / 7, w = tid % 7;
            float efi = 0.f, ec = 0.f, eo = 0.f;
            #pragma unroll
            for (int kh = 0; kh < 3; kh++)
                #pragma unroll
                for (int kw = 0; kw < 3; kw++) {
                    int hh = h + kh - 1, ww = w + kw - 1;
                    if (hh >= 0 && hh < 7 && ww >= 0 && ww < 7) {
                        float aval = ap[hh * 7 + ww];
                        int off = KX + kh * 3 + kw;
                        efi += aval * Wfi[off];
                        ec  += aval * Wc[off];
                        eo  += aval * Wo[off];
                    }
                }
            int base = (t * B_SZ + b) * HW + tid;
            float fi = sigmoidf_(g_preS0[base] + efi + bfi[0]);
            float o  = sigmoidf_(g_preS2[base] + eo + bo[0]);
            float cc = tanhf(g_preS1[base] + ec + bc[0]);
            float cs = fi * csh[tid] + (1.0f - fi) * cc;
            csh[tid] = cs;
            av[tid] = o * tanhf(cs) * g_attmap[base];
        }
        __syncthreads();
        float m = (tid < HW) ? av[tid] : -INFINITY;
        red[tid] = m; __syncthreads();
        for (int s = 32; s > 0; s >>= 1) { if (tid < s) red[tid] = fmaxf(red[tid], red[tid + s]); __syncthreads(); }
        float mx = red[0]; __syncthreads();
        float e = (tid < HW) ? expf(av[tid] - mx) : 0.f;
        red[tid] = e; __syncthreads();
        for (int s = 32; s > 0; s >>= 1) { if (tid < s) red[tid] += red[tid + s]; __syncthreads(); }
        if (tid < HW) {
            g_s[(t * B_SZ + b) * HW + tid] = e / red[0];
            ap[tid] = av[tid];
        }
        __syncthreads();
    }
}

// ---------------------------------------------------------------------------
// x_att scaling (coalesced over c), fp16 in/out
// ---------------------------------------------------------------------------
__global__ void scale_x() {
    size_t lin = (size_t)blockIdx.x * 256 + threadIdx.x;
    if (lin >= (size_t)TB * HW * C_IN) return;
    int c  = lin & (C_IN - 1);
    int rc = (int)(lin >> 11);
    int tb = rc / HW, hw = rc - HW * tb;
    float sc = g_s[rc];
    int p = (hw / 7 + 1) * 9 + (hw % 7) + 1;
    size_t a = (size_t)tb * XROW + (size_t)p * C_IN + c;
    g_xT[a] = __float2half_rn(__half2float(g_xT[a]) * sc);
}

// ---------------------------------------------------------------------------
// FP16 implicit GEMM, 256(M)x128(N)x64(K), 8 warps (4m x 2n), warp 64x64.
// ---------------------------------------------------------------------------
#define STGB2 49152
#define PIPE 3

__global__ __launch_bounds__(256, 1) void conv_gemm_fp16_m256(
    const __half* __restrict__ Apad, int Crow, int cshift, int M, int KT, int Kfull,
    const __half* __restrict__ Wbase, float* __restrict__ Out)
{
    extern __shared__ char smc[];
    const int tid  = threadIdx.x;
    const int m0   = blockIdx.y * 256;
    const int gate = blockIdx.x >> 2;
    const int n0in = (blockIdx.x & 3) * 128;
    const __half* Wg = Wbase + ((size_t)gate * MEM_SZ + n0in) * Kfull;

    const int rlo = tid >> 3;
    const int kq  = (tid & 7) * 8;
    const int stChunk = ((tid & 7) ^ (rlo & 7)) << 4;

    size_t rowoff[8]; int asz[8];
    #pragma unroll
    for (int i = 0; i < 8; i++) {
        int m = m0 + rlo + 32 * i;
        if (m < M) {
            int tb = m / HW, hw = m - HW * tb;
            rowoff[i] = ((size_t)tb * PADHW + (size_t)((hw / 7) * 9 + hw % 7)) * Crow;
            asz[i] = 16;
        } else { rowoff[i] = 0; asz[i] = 0; }
    }

    const int lane = tid & 31;
    const int wid  = tid >> 5;
    const int g    = lane >> 2;
    const int cq   = lane & 3;
    const int wmB  = (wid & 3) * 64;
    const int wnB  = (wid >> 2) * 64;

    float acc[4][8][4];
    #pragma unroll
    for (int a = 0; a < 4; a++)
        #pragma unroll
        for (int b = 0; b < 8; b++)
            #pragma unroll
            for (int c = 0; c < 4; c++) acc[a][b][c] = 0.f;

    auto issue = [&](int s, int kt) {
        char* As_ = smc + s * STGB2;
        char* Bs_ = As_ + 32768;
        uint32_t aB = (uint32_t)__cvta_generic_to_shared(As_);
        uint32_t bB = (uint32_t)__cvta_generic_to_shared(Bs_);
        int k0  = kt * 64;
        int tap = k0 >> cshift;
        int c0  = k0 & (Crow - 1);
        int dr  = tap / 3, dc = tap - 3 * dr;
        size_t poff = (size_t)(dr * 9 + dc) * Crow + c0 + kq;
        #pragma unroll
        for (int i = 0; i < 8; i++) {
            const __half* src = Apad + rowoff[i] + poff;
            uint32_t dst = aB + (uint32_t)((rlo + 32 * i) * 128 + stChunk);
            asm volatile("cp.async.cg.shared.global [%0], [%1], 16, %2;\n"
                         :: "r"(dst), "l"(src), "r"(asz[i]));
        }
        #pragma unroll
        for (int i = 0; i < 4; i++) {
            int nl = rlo + 32 * i;
            const __half* src = Wg + (size_t)nl * Kfull + k0 + kq;
            uint32_t dst = bB + (uint32_t)(nl * 128 + stChunk);
            asm volatile("cp.async.cg.shared.global [%0], [%1], 16;\n"
                         :: "r"(dst), "l"(src));
        }
        asm volatile("cp.async.commit_group;\n");
    };

    #pragma unroll
    for (int s = 0; s < PIPE - 1; s++)
        if (s < KT) issue(s, s);

    for (int kt = 0; kt < KT; kt++) {
        if (kt + 1 < KT) asm volatile("cp.async.wait_group 1;\n" ::: "memory");
        else             asm volatile("cp.async.wait_group 0;\n" ::: "memory");
        __syncthreads();
        if (kt + PIPE - 1 < KT) issue((kt + PIPE - 1) % PIPE, kt + PIPE - 1);

        const char* As_ = smc + (kt % PIPE) * STGB2;
        const char* Bs_ = As_ + 32768;

        #pragma unroll
        for (int ks = 0; ks < 4; ks++) {
            const int ch0 = (((2 * ks)     ^ g) << 4) + 4 * cq;
            const int ch1 = (((2 * ks + 1) ^ g) << 4) + 4 * cq;
            unsigned af[4][4], bf[8][2];
            #pragma unroll
            for (int mt = 0; mt < 4; mt++) {
                const char* r0p = As_ + (wmB + mt * 16 + g) * 128;
                const char* r1p = r0p + 8 * 128;
                af[mt][0] = *(const uint32_t*)(r0p + ch0);
                af[mt][1] = *(const uint32_t*)(r1p + ch0);
                af[mt][2] = *(const uint32_t*)(r0p + ch1);
                af[mt][3] = *(const uint32_t*)(r1p + ch1);
            }
            #pragma unroll
            for (int nt = 0; nt < 8; nt++) {
                const char* np = Bs_ + (wnB + nt * 8 + g) * 128;
                bf[nt][0] = *(const uint32_t*)(np + ch0);
                bf[nt][1] = *(const uint32_t*)(np + ch1);
            }
            #pragma unroll
            for (int mt = 0; mt < 4; mt++)
                #pragma unroll
                for (int nt = 0; nt < 8; nt++) {
                    asm volatile(
                        "mma.sync.aligned.m16n8k16.row.col.f32.f16.f16.f32 "
                        "{%0,%1,%2,%3}, {%4,%5,%6,%7}, {%8,%9}, {%0,%1,%2,%3};\n"
                        : "+f"(acc[mt][nt][0]), "+f"(acc[mt][nt][1]),
                          "+f"(acc[mt][nt][2]), "+f"(acc[mt][nt][3])
                        : "r"(af[mt][0]), "r"(af[mt][1]), "r"(af[mt][2]), "r"(af[mt][3]),
                          "r"(bf[nt][0]), "r"(bf[nt][1]));
                }
        }
        __syncthreads();
    }

    const size_t colBase = (size_t)(gate * MEM_SZ + n0in);
    #pragma unroll
    for (int mt = 0; mt < 4; mt++) {
        int r0 = m0 + wmB + mt * 16 + g;
        #pragma unroll
        for (int nt = 0; nt < 8; nt++) {
            size_t co = colBase + wnB + nt * 8 + cq * 2;
            if (r0 < M) {
                float2 v = make_float2(acc[mt][nt][0], acc[mt][nt][1]);
                *(float2*)&Out[(size_t)r0 * NFUSED + co] = v;
            }
            if (r0 + 8 < M) {
                float2 v = make_float2(acc[mt][nt][2], acc[mt][nt][3]);
                *(float2*)&Out[(size_t)(r0 + 8) * NFUSED + co] = v;
            }
        }
    }
}

// ---------------------------------------------------------------------------
// h-chain: fused h-GEMM (128m x 192n-eff [64n x 3 gates] x 64k) + gate epilogue
// ---------------------------------------------------------------------------
#define HST   40960
#define HSMEM (PIPE * HST)
#define OST   196

__global__ __launch_bounds__(256, 1) void h_gemm_gates(
    int t, const float* __restrict__ bfi, const float* __restrict__ bc,
    const float* __restrict__ bo)
{
    extern __shared__ char smc[];
    const int tid = threadIdx.x;
    const int nb  = blockIdx.x;
    const int m0  = blockIdx.y * 128;

    const int rlo = tid >> 3;
    const int kq  = (tid & 7) * 8;
    const int stChunk = ((tid & 7) ^ (rlo & 7)) << 4;

    size_t rowoff[4]; int asz[4];
    #pragma unroll
    for (int i = 0; i < 4; i++) {
        int m = m0 + rlo + 32 * i;
        if (m < MSTEP) {
            int b = m / HW, hw = m - HW * b;
            rowoff[i] = ((size_t)b * PADHW + (size_t)((hw / 7) * 9 + hw % 7)) * MEM_SZ;
            asz[i] = 16;
        } else { rowoff[i] = 0; asz[i] = 0; }
    }
    const __half* bsrc[6];
    #pragma unroll
    for (int i = 0; i < 6; i++) {
        int j = rlo + 32 * i;
        int gate = j >> 6, jj = j & 63;
        bsrc[i] = g_wh + ((size_t)(gate * MEM_SZ + nb * 64 + jj)) * KH;
    }

    const int lane = tid & 31;
    const int wid  = tid >> 5;
    const int g    = lane >> 2;
    const int cq   = lane & 3;
    const int wmB  = (wid & 1) * 64;
    const int wnB  = (wid >> 1) * 48;

    float acc[4][6][4];
    #pragma unroll
    for (int a = 0; a < 4; a++)
        #pragma unroll
        for (int b = 0; b < 6; b++)
            #pragma unroll
            for (int c = 0; c < 4; c++) acc[a][b][c] = 0.f;

    auto issue = [&](int s, int kt) {
        char* As_ = smc + s * HST;
        char* Bs_ = As_ + 16384;
        uint32_t aB = (uint32_t)__cvta_generic_to_shared(As_);
        uint32_t bB = (uint32_t)__cvta_generic_to_shared(Bs_);
        int k0  = kt * 64;
        int tap = k0 >> 9;
        int c0  = k0 & (MEM_SZ - 1);
        int dr  = tap / 3, dc = tap - 3 * dr;
        size_t poff = (size_t)(dr * 9 + dc) * MEM_SZ + c0 + kq;
        #pragma unroll
        for (int i = 0; i < 4; i++) {
            const __half* src = g_hT + rowoff[i] + poff;
            uint32_t dst = aB + (uint32_t)((rlo + 32 * i) * 128 + stChunk);
            asm volatile("cp.async.cg.shared.global [%0], [%1], 16, %2;\n"
                         :: "r"(dst), "l"(src), "r"(asz[i]));
        }
        #pragma unroll
        for (int i = 0; i < 6; i++) {
            const __half* src = bsrc[i] + k0 + kq;
            uint32_t dst = bB + (uint32_t)((rlo + 32 * i) * 128 + stChunk);
            asm volatile("cp.async.cg.shared.global [%0], [%1], 16;\n"
                         :: "r"(dst), "l"(src));
        }
        asm volatile("cp.async.commit_group;\n");
    };

    const int KT = KH / 64;
    #pragma unroll
    for (int s = 0; s < PIPE - 1; s++) issue(s, s);

    for (int kt = 0; kt < KT; kt++) {
        if (kt + 1 < KT) asm volatile("cp.async.wait_group 1;\n" ::: "memory");
        else             asm volatile("cp.async.wait_group 0;\n" ::: "memory");
        __syncthreads();
        if (kt + PIPE - 1 < KT) issue((kt + PIPE - 1) % PIPE, kt + PIPE - 1);

        const char* As_ = smc + (kt % PIPE) * HST;
        const char* Bs_ = As_ + 16384;

        #pragma unroll
        for (int ks = 0; ks < 4; ks++) {
            const int ch0 = (((2 * ks)     ^ g) << 4) + 4 * cq;
            const int ch1 = (((2 * ks + 1) ^ g) << 4) + 4 * cq;
            unsigned af[4][4], bf[6][2];
            #pragma unroll
            for (int mt = 0; mt < 4; mt++) {
                const char* r0p = As_ + (wmB + mt * 16 + g) * 128;
                const char* r1p = r0p + 8 * 128;
                af[mt][0] = *(const uint32_t*)(r0p + ch0);
                af[mt][1] = *(const uint32_t*)(r1p + ch0);
                af[mt][2] = *(const uint32_t*)(r0p + ch1);
                af[mt][3] = *(const uint32_t*)(r1p + ch1);
            }
            #pragma unroll
            for (int nt = 0; nt < 6; nt++) {
                const char* np = Bs_ + (wnB + nt * 8 + g) * 128;
                bf[nt][0] = *(const uint32_t*)(np + ch0);
                bf[nt][1] = *(const uint32_t*)(np + ch1);
            }
            #pragma unroll
            for (int mt = 0; mt < 4; mt++)
                #pragma unroll
                for (int nt = 0; nt < 6; nt++) {
                    asm volatile(
                        "mma.sync.aligned.m16n8k16.row.col.f32.f16.f16.f32 "
                        "{%0,%1,%2,%3}, {%4,%5,%6,%7}, {%8,%9}, {%0,%1,%2,%3};\n"
                        : "+f"(acc[mt][nt][0]), "+f"(acc[mt][nt][1]),
                          "+f"(acc[mt][nt][2]), "+f"(acc[mt][nt][3])
                        : "r"(af[mt][0]), "r"(af[mt][1]), "r"(af[mt][2]), "r"(af[mt][3]),
                          "r"(bf[nt][0]), "r"(bf[nt][1]));
                }
        }
        __syncthreads();
    }

    // ---- epilogue: stash GEMM tile in smem, then fused gate update ----
    float* Osm = (float*)smc;
    #pragma unroll
    for (int mt = 0; mt < 4; mt++) {
        int r = wmB + mt * 16 + g;
        #pragma unroll
        for (int nt = 0; nt < 6; nt++) {
            int co = wnB + nt * 8 + cq * 2;
            *(float2*)&Osm[r * OST + co]       = make_float2(acc[mt][nt][0], acc[mt][nt][1]);
            *(float2*)&Osm[(r + 8) * OST + co] = make_float2(acc[mt][nt][2], acc[mt][nt][3]);
        }
    }
    __syncthreads();

    #pragma unroll
    for (int it = 0; it < 32; it++) {
        int idx = tid + 256 * it;
        int ml = idx >> 6, nl = idx & 63;
        int m = m0 + ml;
        if (m >= MSTEP) continue;
        float g0 = Osm[ml * OST + nl];
        float g1 = Osm[ml * OST + 64 + nl];
        float g2 = Osm[ml * OST + 128 + nl];
        int n = nb * 64 + nl;
        size_t pOff = ((size_t)(t * MSTEP + m)) * NFUSED;
        float pfi = g_preM[pOff + n]        + g0 + bfi[n];
        float pc  = g_preM[pOff + 512 + n]  + g1 + bc[n];
        float po  = g_preM[pOff + 1024 + n] + g2 + bo[n];
        float fi = sigmoidf_(pfi);
        float o  = sigmoidf_(po);
        int lin = m * MEM_SZ + n;
        float cn = fi * g_cstate[lin] + (1.0f - fi) * tanhf(pc);
        g_cstate[lin] = cn;
        float h = o * tanhf(cn);
        int b = m / HW, hw = m - HW * b;
        int p = (hw / 7 + 1) * 9 + (hw % 7) + 1;
        g_hT[(size_t)b * HROW + (size_t)p * MEM_SZ + n] = __float2half_rn(h);
    }
}

// ---------------------------------------------------------------------------
// Step 0 gate update (h = 0, cstate = 0 -> no h-GEMM needed)
// ---------------------------------------------------------------------------
__global__ void gate0_kernel(const float* __restrict__ bfi,
                             const float* __restrict__ bc, const float* __restrict__ bo) {
    int lin = blockIdx.x * 256 + threadIdx.x;
    if (lin >= MSTEP * MEM_SZ) return;
    int n = lin & (MEM_SZ - 1);
    int m = lin >> 9;
    int b = m / HW, hw = m - HW * b;
    size_t pOff = (size_t)m * NFUSED;
    float pfi = g_preM[pOff + n]        + bfi[n];
    float pc  = g_preM[pOff + 512 + n]  + bc[n];
    float po  = g_preM[pOff + 1024 + n] + bo[n];
    float fi = sigmoidf_(pfi);
    float o  = sigmoidf_(po);
    float cn = (1.0f - fi) * tanhf(pc);
    g_cstate[lin] = cn;
    float h = o * tanhf(cn);
    int p = (hw / 7 + 1) * 9 + (hw % 7) + 1;
    g_hT[(size_t)b * HROW + (size_t)p * MEM_SZ + n] = __float2half_rn(h);
}

// ---------------------------------------------------------------------------
// Final: feats = mean_hw(h); logits = feats @ W_fc^T + b_fc
// ---------------------------------------------------------------------------
__global__ void final_kernel(const float* __restrict__ W_fc, const float* __restrict__ b_fc,
                             float* __restrict__ logitsOut, float* __restrict__ featsOut) {
    int b = blockIdx.x, n = threadIdx.x;
    const __half* hb = &g_hT[(size_t)b * HROW];
    float s = 0.f;
    #pragma unroll
    for (int hh = 1; hh <= 7; hh++)
        #pragma unroll
        for (int ww = 1; ww <= 7; ww++) s += __half2float(hb[(size_t)(hh * 9 + ww) * MEM_SZ + n]);
    float f = s * (1.0f / 49.0f);
    __shared__ float fs[MEM_SZ];
    fs[n] = f;
    if (featsOut) featsOut[b * MEM_SZ + n] = f;
    __syncthreads();
    if (n < N_CLS && logitsOut) {
        float acc = b_fc[n];
        for (int k = 0; k < MEM_SZ; k++) acc += fs[k] * W_fc[n * MEM_SZ + k];
        logitsOut[b * N_CLS + n] = acc;
    }
}

// ---------------------------------------------------------------------------
// Host launcher with fork-join stream overlap
// ---------------------------------------------------------------------------
extern "C" void kernel_launch(void* const* d_in, const int* in_sizes, int n_in,
                              void* d_out, int out_size) {
    const float* x     = (const float*)d_in[0];
    const float* W_fi  = (const float*)d_in[1];
    const float* b_fi  = (const float*)d_in[2];
    const float* W_c   = (const float*)d_in[3];
    const float* b_c   = (const float*)d_in[4];
    const float* W_o   = (const float*)d_in[5];
    const float* b_o   = (const float*)d_in[6];
    const float* Ws_fi = (const float*)d_in[7];
    const float* bs_fi = (const float*)d_in[8];
    const float* Ws_c  = (const float*)d_in[9];
    const float* bs_c  = (const float*)d_in[10];
    const float* Ws_o  = (const float*)d_in[11];
    const float* bs_o  = (const float*)d_in[12];
    const float* W_cam = (const float*)d_in[13];
    const float* W_fc  = (const float*)d_in[14];
    const float* b_fc  = (const float*)d_in[15];

    __half* xT; cudaGetSymbolAddress((void**)&xT, g_xT);
    __half* wx; cudaGetSymbolAddress((void**)&wx, g_wx);
    float*  pm; cudaGetSymbolAddress((void**)&pm, g_preM);

    // one-time host resources (no device memory; identical GPU work each call)
    static cudaStream_t s2 = nullptr;
    static cudaEvent_t evFork = nullptr, evCam = nullptr, evScale = nullptr;
    static cudaEvent_t evChunk[4] = {nullptr, nullptr, nullptr, nullptr};
    if (!s2) {
        cudaStreamCreateWithFlags(&s2, cudaStreamNonBlocking);
        cudaEventCreateWithFlags(&evFork,  cudaEventDisableTiming);
        cudaEventCreateWithFlags(&evCam,   cudaEventDisableTiming);
        cudaEventCreateWithFlags(&evScale, cudaEventDisableTiming);
        for (int i = 0; i < 4; i++)
            cudaEventCreateWithFlags(&evChunk[i], cudaEventDisableTiming);
    }

    const int SMEM_BYTES2 = PIPE * STGB2;
    cudaFuncSetAttribute(conv_gemm_fp16_m256, cudaFuncAttributeMaxDynamicSharedMemorySize, SMEM_BYTES2);
    cudaFuncSetAttribute(h_gemm_gates, cudaFuncAttributeMaxDynamicSharedMemorySize, HSMEM);

    float* outF = (float*)d_out;
    float* lp = nullptr; float* fp = nullptr;
    if (out_size >= B_SZ * N_CLS + B_SZ * MEM_SZ) { lp = outF; fp = outF + B_SZ * N_CLS; }
    else if (out_size == B_SZ * MEM_SZ)           { fp = outF; }
    else                                          { lp = outF; }

    // 1. pad + transpose x (fp16, borders, pooled); reorder weights  [stream 0]
    {
        dim3 grid(TB, C_IN / 32);
        pad_xT_pool<<<grid, 256>>>(x);
    }
    {
        const size_t TOT = (size_t)3 * MEM_SZ * C_IN + (size_t)3 * MEM_SZ * MEM_SZ
                         + (size_t)3 * C_IN + (size_t)B_SZ * HROW + (size_t)MSTEP * MEM_SZ;
        reorder_all<<<(int)((TOT + 255) / 256), 256>>>(W_fi, W_c, W_o, Ws_fi, Ws_c, Ws_o);
    }
    // 2. fork: CAM branch on s2, preS branch on stream 0 (independent until att_fused)
    cudaEventRecord(evFork, 0);
    cudaStreamWaitEvent(s2, evFork, 0);
    {
        dim3 grid((C_CAM + 63) / 64, TB / 64);
        logits_gemm<<<grid, 256, 0, s2>>>(W_cam);
    }
    cam_soft<<<TB, 256, 0, s2>>>(x, W_cam);
    cudaEventRecord(evCam, s2);
    {
        dim3 grid(TB, 9);
        preS_tap<<<grid, 256>>>();
    }
    preS_reduce<<<(MBIG + 255) / 256, 256>>>();
    cudaStreamWaitEvent(0, evCam, 0);   // join CAM branch
    // 3. attention recurrence + scaling  [stream 0]
    att_fused<<<B_SZ, 64>>>(Ws_fi, Ws_c, Ws_o, bs_fi, bs_c, bs_o);
    scale_x<<<(int)(((size_t)TB * HW * C_IN + 255) / 256), 256>>>();
    // 4. big GEMM in 4 timestep-chunks on s2 (each covers 4 timesteps)
    cudaEventRecord(evScale, 0);
    cudaStreamWaitEvent(s2, evScale, 0);
    const int MCHUNK = 4 * MSTEP;   // 6272 rows
    for (int c = 0; c < 4; c++) {
        dim3 grid(12, (MCHUNK + 255) / 256);
        conv_gemm_fp16_m256<<<grid, 256, SMEM_BYTES2, s2>>>(
            xT + (size_t)(4 * c * B_SZ) * XROW, C_IN, 11, MCHUNK, KX / 64, KX,
            wx, pm + (size_t)(4 * c) * MSTEP * NFUSED);
        cudaEventRecord(evChunk[c], s2);
    }
    // 5. h-chain on stream 0, overlapping chunks 1-3 of the big GEMM
    cudaStreamWaitEvent(0, evChunk[0], 0);
    gate0_kernel<<<(MSTEP * MEM_SZ + 255) / 256, 256>>>(b_fi, b_c, b_o);
    for (int t = 1; t < T_STEPS; t++) {
        if ((t & 3) == 0) cudaStreamWaitEvent(0, evChunk[t >> 2], 0);
        dim3 grid(8, (MSTEP + 127) / 128);
        h_gemm_gates<<<grid, 256, HSMEM>>>(t, b_fi, b_c, b_o);
    }
    cudaStreamWaitEvent(0, evChunk[3], 0);   // explicit join of s2
    // 6. final pooling + FC head
    final_kernel<<<B_SZ, MEM_SZ>>>(W_fc, b_fc, lp, fp);
}